// round 5
// baseline (speedup 1.0000x reference)
#include <cuda_runtime.h>
#include <math.h>

#define EMBED 1024
#define HEADS 16
#define HD    64
#define BATCH 2
#define SEQ   2048
#define MROWS (BATCH*SEQ)   /* 4096 */

// ---------------------------------------------------------------------------
// Scratch (device globals: allocation-free per harness rules)
// ---------------------------------------------------------------------------
__device__ float g_Q [BATCH*HEADS*SEQ*HD];   // [B,H,S,Dh]
__device__ float g_K [BATCH*HEADS*SEQ*HD];   // [B,H,S,Dh]
__device__ float g_Vt[BATCH*HEADS*HD*SEQ];   // [B,H,Dh,S]  (V transposed)
__device__ float g_A [MROWS*EMBED];          // attention output, [B*S, E]

// ---------------------------------------------------------------------------
// TF32 helpers
// ---------------------------------------------------------------------------
__device__ __forceinline__ unsigned f2tf(float f) {
    unsigned u; asm("cvt.rna.tf32.f32 %0, %1;" : "=r"(u) : "f"(f)); return u;
}
__device__ __forceinline__ uint4 tf4(float4 v) {
    uint4 u; u.x = f2tf(v.x); u.y = f2tf(v.y); u.z = f2tf(v.z); u.w = f2tf(v.w);
    return u;
}
// D(16x8,f32) += A(16x8,tf32,row) * B(8x8,tf32,col)
__device__ __forceinline__ void mma8(float* c, const unsigned* a, const unsigned* b) {
    asm volatile(
        "mma.sync.aligned.m16n8k8.row.col.f32.tf32.tf32.f32 "
        "{%0,%1,%2,%3},{%4,%5,%6,%7},{%8,%9},{%0,%1,%2,%3};\n"
        : "+f"(c[0]), "+f"(c[1]), "+f"(c[2]), "+f"(c[3])
        : "r"(a[0]), "r"(a[1]), "r"(a[2]), "r"(a[3]), "r"(b[0]), "r"(b[1]));
}

// Fragment layouts (verified against CUTLASS SM80_16x8x8_F32TF32TF32F32_TN):
//   gid = lane>>2, tig = lane&3
//   A: a0(m=gid,  k=tig)  a1(m=gid+8, k=tig)  a2(m=gid, k=tig+4)  a3(m=gid+8, k=tig+4)
//   B: b0(k=tig,  n=gid)  b1(k=tig+4, n=gid)
//   C: c0(m=gid, n=2tig)  c1(m=gid, n=2tig+1) c2(m=gid+8, n=2tig) c3(m=gid+8, n=2tig+1)

// ---------------------------------------------------------------------------
// GEMM: C[M=4096, N=1024] = A[4096,1024] @ W[1024,1024] + bias
// Block tile 128x128x32; 8 warps (2x4), warp tile 64x32.
// mode 0: write [B,H,S,Dh]   (Q / K)
// mode 2: write [B,H,Dh,S]   (V transposed)
// mode 3: write row-major [M,N] (output projection)
// ---------------------------------------------------------------------------
#define BM 128
#define BN 128
#define BK 32

__global__ void __launch_bounds__(256, 2)
gemm_tf32(const float* __restrict__ A, const float* __restrict__ W,
          const float* __restrict__ bias, float* __restrict__ out, int mode)
{
    __shared__ __align__(16) unsigned As[BM][BK + 4];   // [m][k], stride 36
    __shared__ __align__(16) unsigned Bs[BK][BN + 4];   // [k][n], stride 132

    const int tid  = threadIdx.x;
    const int w    = tid >> 5;
    const int lane = tid & 31;
    const int gid  = lane >> 2;
    const int tig  = lane & 3;
    const int wm   = w >> 2;            // 0..1
    const int wn   = w & 3;             // 0..3
    const int m0   = blockIdx.y * BM;
    const int n0   = blockIdx.x * BN;

    float acc[4][4][4];
#pragma unroll
    for (int i = 0; i < 4; i++)
#pragma unroll
        for (int j = 0; j < 4; j++)
#pragma unroll
            for (int r = 0; r < 4; r++) acc[i][j][r] = 0.f;

    for (int k0 = 0; k0 < EMBED; k0 += BK) {
        // A tile: 128 rows x 32 k, float4 along k (contiguous), direct store
#pragma unroll
        for (int it = 0; it < 4; it++) {
            int idx = tid + it * 256;            // 0..1023
            int r = idx >> 3, c4 = idx & 7;
            float4 v = *reinterpret_cast<const float4*>(
                &A[(size_t)(m0 + r) * EMBED + k0 + c4 * 4]);
            *reinterpret_cast<uint4*>(&As[r][c4 * 4]) = tf4(v);
        }
        // B tile: 32 k-rows x 128 n, float4 along n (contiguous), direct store
#pragma unroll
        for (int it = 0; it < 4; it++) {
            int idx = tid + it * 256;
            int r = idx >> 5, c4 = idx & 31;
            float4 v = *reinterpret_cast<const float4*>(
                &W[(size_t)(k0 + r) * EMBED + n0 + c4 * 4]);
            *reinterpret_cast<uint4*>(&Bs[r][c4 * 4]) = tf4(v);
        }
        __syncthreads();

#pragma unroll
        for (int kk = 0; kk < BK; kk += 8) {
            unsigned af[4][4], bf[4][2];
#pragma unroll
            for (int i = 0; i < 4; i++) {
                int mb = wm * 64 + i * 16;
                af[i][0] = As[mb + gid    ][kk + tig    ];
                af[i][1] = As[mb + gid + 8][kk + tig    ];
                af[i][2] = As[mb + gid    ][kk + tig + 4];
                af[i][3] = As[mb + gid + 8][kk + tig + 4];
            }
#pragma unroll
            for (int j = 0; j < 4; j++) {
                int nb = wn * 32 + j * 8;
                bf[j][0] = Bs[kk + tig    ][nb + gid];
                bf[j][1] = Bs[kk + tig + 4][nb + gid];
            }
#pragma unroll
            for (int i = 0; i < 4; i++)
#pragma unroll
                for (int j = 0; j < 4; j++)
                    mma8(acc[i][j], af[i], bf[j]);
        }
        __syncthreads();
    }

    // Epilogue
#pragma unroll
    for (int i = 0; i < 4; i++) {
#pragma unroll
        for (int j = 0; j < 4; j++) {
#pragma unroll
            for (int r = 0; r < 4; r++) {
                int m = m0 + wm * 64 + i * 16 + gid + ((r >> 1) << 3);
                int n = n0 + wn * 32 + j * 8 + 2 * tig + (r & 1);
                float v = acc[i][j][r] + bias[n];
                if (mode == 3) {
                    out[(size_t)m * EMBED + n] = v;
                } else {
                    int b = m >> 11, s = m & (SEQ - 1);
                    int h = n >> 6,  d = n & (HD - 1);
                    if (mode == 2)
                        out[(((size_t)(b * HEADS + h)) * HD + d) * SEQ + s] = v;
                    else
                        out[(((size_t)(b * HEADS + h)) * SEQ + s) * HD + d] = v;
                }
            }
        }
    }
}

// ---------------------------------------------------------------------------
// Flash attention: one CTA = 128 q-rows of one (b,h); loop over 64-wide kv
// blocks with online softmax. 8 warps; warp owns 16 q-rows x all 64 cols.
// Scale 1/sqrt(Dh)=0.125 folded into Q load.
// ---------------------------------------------------------------------------
#define BQ  128
#define BKV 64
#define FL_STRIDE 68   // 64 + 4 pad -> conflict-free (gid*4+tig) fragment loads
#define FLASH_SMEM_WORDS (BQ*FL_STRIDE + BKV*FL_STRIDE + HD*FL_STRIDE + BQ*FL_STRIDE)
#define FLASH_SMEM_BYTES (FLASH_SMEM_WORDS * 4)   /* 104448 */

__global__ void __launch_bounds__(256, 1)
flash_attn(const float* __restrict__ Q, const float* __restrict__ K,
           const float* __restrict__ Vt, float* __restrict__ outA)
{
    extern __shared__ unsigned sh[];
    unsigned (*Qs)[FL_STRIDE]  = (unsigned (*)[FL_STRIDE])(sh);                              // [q=128][d=64]
    unsigned (*Ks)[FL_STRIDE]  = (unsigned (*)[FL_STRIDE])(sh + BQ * FL_STRIDE);             // [kv=64][d=64]
    unsigned (*Vts)[FL_STRIDE] = (unsigned (*)[FL_STRIDE])(sh + (BQ + BKV) * FL_STRIDE);     // [d=64][kv=64]
    unsigned (*Ps)[FL_STRIDE]  = (unsigned (*)[FL_STRIDE])(sh + (BQ + BKV + HD) * FL_STRIDE);// [q=128][kv=64]

    const int tid  = threadIdx.x;
    const int w    = tid >> 5;
    const int lane = tid & 31;
    const int gid  = lane >> 2;
    const int tig  = lane & 3;
    const int bh   = blockIdx.y;            // 0..31  (b*16+h)
    const int q0   = blockIdx.x * BQ;
    const int mq   = w * 16;                // warp's local q base

    const float* Qp = Q  + (size_t)bh * SEQ * HD;
    const float* Kp = K  + (size_t)bh * SEQ * HD;
    const float* Vp = Vt + (size_t)bh * HD * SEQ;

    // Load Q tile (scaled by 1/sqrt(Dh)), tf32-converted
#pragma unroll
    for (int it = 0; it < 8; it++) {
        int idx = tid + it * 256;           // 0..2047 float4s
        int r = idx >> 4, c4 = idx & 15;
        float4 v = *reinterpret_cast<const float4*>(&Qp[(size_t)(q0 + r) * HD + c4 * 4]);
        v.x *= 0.125f; v.y *= 0.125f; v.z *= 0.125f; v.w *= 0.125f;
        *reinterpret_cast<uint4*>(&Qs[r][c4 * 4]) = tf4(v);
    }

    float o[8][4];
#pragma unroll
    for (int j = 0; j < 8; j++)
#pragma unroll
        for (int r = 0; r < 4; r++) o[j][r] = 0.f;
    float mrow[2] = {-1e30f, -1e30f};
    float lrow[2] = {0.f, 0.f};

    for (int kb = 0; kb < SEQ / BKV; kb++) {
        const int s0 = kb * BKV;
        // Load K tile [64 kv][64 d] and Vt tile [64 d][64 kv]
#pragma unroll
        for (int it = 0; it < 4; it++) {
            int idx = tid + it * 256;       // 0..1023 float4s
            int r = idx >> 4, c4 = idx & 15;
            float4 v = *reinterpret_cast<const float4*>(&Kp[(size_t)(s0 + r) * HD + c4 * 4]);
            *reinterpret_cast<uint4*>(&Ks[r][c4 * 4]) = tf4(v);
        }
#pragma unroll
        for (int it = 0; it < 4; it++) {
            int idx = tid + it * 256;
            int r = idx >> 4, c4 = idx & 15;
            float4 v = *reinterpret_cast<const float4*>(&Vp[(size_t)r * SEQ + s0 + c4 * 4]);
            *reinterpret_cast<uint4*>(&Vts[r][c4 * 4]) = tf4(v);
        }
        __syncthreads();

        // S = (Q*scale) @ K^T  : warp computes 16 x 64
        float s[8][4];
#pragma unroll
        for (int j = 0; j < 8; j++)
#pragma unroll
            for (int r = 0; r < 4; r++) s[j][r] = 0.f;

#pragma unroll
        for (int kk = 0; kk < HD; kk += 8) {
            unsigned a[4];
            a[0] = Qs[mq + gid    ][kk + tig    ];
            a[1] = Qs[mq + gid + 8][kk + tig    ];
            a[2] = Qs[mq + gid    ][kk + tig + 4];
            a[3] = Qs[mq + gid + 8][kk + tig + 4];
#pragma unroll
            for (int j = 0; j < 8; j++) {
                unsigned b[2] = { Ks[j * 8 + gid][kk + tig],
                                  Ks[j * 8 + gid][kk + tig + 4] };
                mma8(s[j], a, b);
            }
        }

        // Online softmax: thread handles rows (gid) [regs 0,1] and (gid+8) [regs 2,3]
#pragma unroll
        for (int rr = 0; rr < 2; rr++) {
            float mx = -1e30f;
#pragma unroll
            for (int j = 0; j < 8; j++) {
                mx = fmaxf(mx, s[j][rr * 2]);
                mx = fmaxf(mx, s[j][rr * 2 + 1]);
            }
            mx = fmaxf(mx, __shfl_xor_sync(0xffffffffu, mx, 1));
            mx = fmaxf(mx, __shfl_xor_sync(0xffffffffu, mx, 2));
            float mnew = fmaxf(mrow[rr], mx);
            float corr = __expf(mrow[rr] - mnew);
            float rs = 0.f;
#pragma unroll
            for (int j = 0; j < 8; j++) {
                float e0 = __expf(s[j][rr * 2]     - mnew);
                float e1 = __expf(s[j][rr * 2 + 1] - mnew);
                s[j][rr * 2] = e0; s[j][rr * 2 + 1] = e1;
                rs += e0 + e1;
            }
            rs += __shfl_xor_sync(0xffffffffu, rs, 1);
            rs += __shfl_xor_sync(0xffffffffu, rs, 2);
            lrow[rr] = lrow[rr] * corr + rs;
            mrow[rr] = mnew;
#pragma unroll
            for (int j = 0; j < 8; j++) {
                o[j][rr * 2]     *= corr;
                o[j][rr * 2 + 1] *= corr;
            }
        }

        // P -> shared (C-fragment layout != A-fragment layout for tf32)
#pragma unroll
        for (int j = 0; j < 8; j++) {
            Ps[mq + gid    ][j * 8 + 2 * tig    ] = f2tf(s[j][0]);
            Ps[mq + gid    ][j * 8 + 2 * tig + 1] = f2tf(s[j][1]);
            Ps[mq + gid + 8][j * 8 + 2 * tig    ] = f2tf(s[j][2]);
            Ps[mq + gid + 8][j * 8 + 2 * tig + 1] = f2tf(s[j][3]);
        }
        __syncwarp();

        // O += P @ V   (B operand = Vt[d][kv], col-major over k=kv)
#pragma unroll
        for (int kk = 0; kk < BKV; kk += 8) {
            unsigned a[4];
            a[0] = Ps[mq + gid    ][kk + tig    ];
            a[1] = Ps[mq + gid + 8][kk + tig    ];
            a[2] = Ps[mq + gid    ][kk + tig + 4];
            a[3] = Ps[mq + gid + 8][kk + tig + 4];
#pragma unroll
            for (int j = 0; j < 8; j++) {
                unsigned b[2] = { Vts[j * 8 + gid][kk + tig],
                                  Vts[j * 8 + gid][kk + tig + 4] };
                mma8(o[j], a, b);
            }
        }
        __syncthreads();   // guard Ks/Vts reuse next iteration
    }

    // Epilogue: O /= l, write to concat layout [B*S, E] at column h*64+d
    const int b = bh >> 4, h = bh & 15;
    const float inv0 = 1.f / lrow[0];
    const float inv1 = 1.f / lrow[1];
    const int row0 = q0 + mq + gid;
    const int row1 = row0 + 8;
#pragma unroll
    for (int j = 0; j < 8; j++) {
        int col = h * HD + j * 8 + 2 * tig;
        outA[(size_t)(b * SEQ + row0) * EMBED + col    ] = o[j][0] * inv0;
        outA[(size_t)(b * SEQ + row0) * EMBED + col + 1] = o[j][1] * inv0;
        outA[(size_t)(b * SEQ + row1) * EMBED + col    ] = o[j][2] * inv1;
        outA[(size_t)(b * SEQ + row1) * EMBED + col + 1] = o[j][3] * inv1;
    }
}

// ---------------------------------------------------------------------------
// Launch
// ---------------------------------------------------------------------------
extern "C" void kernel_launch(void* const* d_in, const int* in_sizes, int n_in,
                              void* d_out, int out_size)
{
    const float* X  = (const float*)d_in[0];
    const float* Wq = (const float*)d_in[1];
    const float* bq = (const float*)d_in[2];
    const float* Wk = (const float*)d_in[3];
    const float* bk = (const float*)d_in[4];
    const float* Wv = (const float*)d_in[5];
    const float* bv = (const float*)d_in[6];
    const float* Wo = (const float*)d_in[7];
    const float* bo = (const float*)d_in[8];
    float* out = (float*)d_out;

    float *qb, *kb, *vtb, *ab;
    cudaGetSymbolAddress((void**)&qb,  g_Q);
    cudaGetSymbolAddress((void**)&kb,  g_K);
    cudaGetSymbolAddress((void**)&vtb, g_Vt);
    cudaGetSymbolAddress((void**)&ab,  g_A);

    cudaFuncSetAttribute(flash_attn, cudaFuncAttributeMaxDynamicSharedMemorySize,
                         FLASH_SMEM_BYTES);

    dim3 ggrid(EMBED / BN, MROWS / BM);   // (8, 32)
    gemm_tf32<<<ggrid, 256>>>(X, Wq, bq, qb,  0);
    gemm_tf32<<<ggrid, 256>>>(X, Wk, bk, kb,  0);
    gemm_tf32<<<ggrid, 256>>>(X, Wv, bv, vtb, 2);

    dim3 fgrid(SEQ / BQ, BATCH * HEADS);  // (16, 32)
    flash_attn<<<fgrid, 256, FLASH_SMEM_BYTES>>>(qb, kb, vtb, ab);

    gemm_tf32<<<ggrid, 256>>>(ab, Wo, bo, out, 3);
}

// round 6
// speedup vs baseline: 1.1898x; 1.1898x over previous
#include <cuda_runtime.h>
#include <math.h>

#define EMBED 1024
#define HEADS 16
#define HD    64
#define BATCH 2
#define SEQ   2048
#define MROWS (BATCH*SEQ)   /* 4096 */

// ---------------------------------------------------------------------------
// Scratch (device globals: allocation-free per harness rules)
// ---------------------------------------------------------------------------
__device__ float g_Q [BATCH*HEADS*SEQ*HD];   // [B,H,S,Dh]
__device__ float g_K [BATCH*HEADS*SEQ*HD];   // [B,H,S,Dh]
__device__ float g_Vt[BATCH*HEADS*HD*SEQ];   // [B,H,Dh,S]  (V transposed)
__device__ float g_A [MROWS*EMBED];          // attention output, [B*S, E]

// ---------------------------------------------------------------------------
// TF32 helpers
// ---------------------------------------------------------------------------
__device__ __forceinline__ unsigned f2tf(float f) {
    unsigned u; asm("cvt.rna.tf32.f32 %0, %1;" : "=r"(u) : "f"(f)); return u;
}
__device__ __forceinline__ uint4 tf4(float4 v) {
    uint4 u; u.x = f2tf(v.x); u.y = f2tf(v.y); u.z = f2tf(v.z); u.w = f2tf(v.w);
    return u;
}
__device__ __forceinline__ float ex2(float x) {
    float y; asm("ex2.approx.f32 %0, %1;" : "=f"(y) : "f"(x)); return y;
}
// D(16x8,f32) += A(16x8,tf32,row) * B(8x8,tf32,col)
__device__ __forceinline__ void mma8(float* c, const unsigned* a, const unsigned* b) {
    asm volatile(
        "mma.sync.aligned.m16n8k8.row.col.f32.tf32.tf32.f32 "
        "{%0,%1,%2,%3},{%4,%5,%6,%7},{%8,%9},{%0,%1,%2,%3};\n"
        : "+f"(c[0]), "+f"(c[1]), "+f"(c[2]), "+f"(c[3])
        : "r"(a[0]), "r"(a[1]), "r"(a[2]), "r"(a[3]), "r"(b[0]), "r"(b[1]));
}

// Fragment layouts (gid = lane>>2, tig = lane&3):
//   A: a0(m=gid,  k=tig)  a1(m=gid+8, k=tig)  a2(m=gid, k=tig+4)  a3(m=gid+8, k=tig+4)
//   B: b0(k=tig,  n=gid)  b1(k=tig+4, n=gid)
//   C: c0(m=gid, n=2tig)  c1(m=gid, n=2tig+1) c2(m=gid+8, n=2tig) c3(m=gid+8, n=2tig+1)

// ---------------------------------------------------------------------------
// GEMM body: C[M=4096, N=1024] = A[4096,1024] @ W[1024,1024] + bias
// Block tile 128x128x32; 8 warps (2x4), warp tile 64x32.
// mode 0: write [B,H,S,Dh]; mode 2: write [B,H,Dh,S]; mode 3: row-major [M,N]
// ---------------------------------------------------------------------------
#define BM 128
#define BN 128
#define BK 32

__device__ __forceinline__ void
gemm_body(const float* __restrict__ A, const float* __restrict__ W,
          const float* __restrict__ bias, float* __restrict__ out, int mode)
{
    __shared__ __align__(16) unsigned As[BM][BK + 4];   // [m][k]
    __shared__ __align__(16) unsigned Bs[BK][BN + 4];   // [k][n]

    const int tid  = threadIdx.x;
    const int w    = tid >> 5;
    const int lane = tid & 31;
    const int gid  = lane >> 2;
    const int tig  = lane & 3;
    const int wm   = w >> 2;            // 0..1
    const int wn   = w & 3;             // 0..3
    const int m0   = blockIdx.y * BM;
    const int n0   = blockIdx.x * BN;

    float acc[4][4][4];
#pragma unroll
    for (int i = 0; i < 4; i++)
#pragma unroll
        for (int j = 0; j < 4; j++)
#pragma unroll
            for (int r = 0; r < 4; r++) acc[i][j][r] = 0.f;

    for (int k0 = 0; k0 < EMBED; k0 += BK) {
#pragma unroll
        for (int it = 0; it < 4; it++) {
            int idx = tid + it * 256;            // 0..1023
            int r = idx >> 3, c4 = idx & 7;
            float4 v = *reinterpret_cast<const float4*>(
                &A[(size_t)(m0 + r) * EMBED + k0 + c4 * 4]);
            *reinterpret_cast<uint4*>(&As[r][c4 * 4]) = tf4(v);
        }
#pragma unroll
        for (int it = 0; it < 4; it++) {
            int idx = tid + it * 256;
            int r = idx >> 5, c4 = idx & 31;
            float4 v = *reinterpret_cast<const float4*>(
                &W[(size_t)(k0 + r) * EMBED + n0 + c4 * 4]);
            *reinterpret_cast<uint4*>(&Bs[r][c4 * 4]) = tf4(v);
        }
        __syncthreads();

#pragma unroll
        for (int kk = 0; kk < BK; kk += 8) {
            unsigned af[4][4], bf[4][2];
#pragma unroll
            for (int i = 0; i < 4; i++) {
                int mb = wm * 64 + i * 16;
                af[i][0] = As[mb + gid    ][kk + tig    ];
                af[i][1] = As[mb + gid + 8][kk + tig    ];
                af[i][2] = As[mb + gid    ][kk + tig + 4];
                af[i][3] = As[mb + gid + 8][kk + tig + 4];
            }
#pragma unroll
            for (int j = 0; j < 4; j++) {
                int nb = wn * 32 + j * 8;
                bf[j][0] = Bs[kk + tig    ][nb + gid];
                bf[j][1] = Bs[kk + tig + 4][nb + gid];
            }
#pragma unroll
            for (int i = 0; i < 4; i++)
#pragma unroll
                for (int j = 0; j < 4; j++)
                    mma8(acc[i][j], af[i], bf[j]);
        }
        __syncthreads();
    }

#pragma unroll
    for (int i = 0; i < 4; i++) {
#pragma unroll
        for (int j = 0; j < 4; j++) {
#pragma unroll
            for (int r = 0; r < 4; r++) {
                int m = m0 + wm * 64 + i * 16 + gid + ((r >> 1) << 3);
                int n = n0 + wn * 32 + j * 8 + 2 * tig + (r & 1);
                float v = acc[i][j][r] + bias[n];
                if (mode == 3) {
                    out[(size_t)m * EMBED + n] = v;
                } else {
                    int b = m >> 11, s = m & (SEQ - 1);
                    int h = n >> 6,  d = n & (HD - 1);
                    if (mode == 2)
                        out[(((size_t)(b * HEADS + h)) * HD + d) * SEQ + s] = v;
                    else
                        out[(((size_t)(b * HEADS + h)) * SEQ + s) * HD + d] = v;
                }
            }
        }
    }
}

// Fused QKV: blockIdx.z selects the weight/output triple. 768 CTAs in one
// launch fills the chip (3 x 256-CTA launches each under-filled 296 slots).
__global__ void __launch_bounds__(256, 2)
gemm_qkv(const float* __restrict__ X,
         const float* __restrict__ Wq, const float* __restrict__ bq, float* __restrict__ Qo,
         const float* __restrict__ Wk, const float* __restrict__ bk, float* __restrict__ Ko,
         const float* __restrict__ Wv, const float* __restrict__ bv, float* __restrict__ Vo)
{
    if (blockIdx.z == 0)      gemm_body(X, Wq, bq, Qo, 0);
    else if (blockIdx.z == 1) gemm_body(X, Wk, bk, Ko, 0);
    else                      gemm_body(X, Wv, bv, Vo, 2);
}

__global__ void __launch_bounds__(256, 2)
gemm_tf32(const float* __restrict__ A, const float* __restrict__ W,
          const float* __restrict__ bias, float* __restrict__ out, int mode)
{
    gemm_body(A, W, bias, out, mode);
}

// ---------------------------------------------------------------------------
// Flash attention v2:
//  - BQ=64 q-rows, 4 warps (warp = 16 q-rows x 64 kv)
//  - Q fragments held in registers for the whole kv loop (no Q LDS in loop)
//  - P C-frag -> A-frag via warp shuffles (no Ps smem, no syncwarp)
//  - base-2 softmax (log2e folded into Q scale; raw ex2.approx)
//  - double-buffered K/V tiles, next-tile LDG prefetched into registers
//    behind the mma phases; ONE __syncthreads per kv block
//  - smem 68 KB x occ 3 (reg-limited), vs 104 KB x occ 1 before
// ---------------------------------------------------------------------------
#define BQ  64
#define BKV 64
#define FL_STRIDE 68                       // 64 + 4 pad, conflict-free frags
#define TILE_WORDS (BKV * FL_STRIDE)       // 4352
#define FLASH_SMEM_WORDS (4 * TILE_WORDS)  // K0 V0 K1 V1
#define FLASH_SMEM_BYTES (FLASH_SMEM_WORDS * 4)   /* 69632 */

__global__ void __launch_bounds__(128, 3)
flash_attn(const float* __restrict__ Q, const float* __restrict__ K,
           const float* __restrict__ Vt, float* __restrict__ outA)
{
    extern __shared__ unsigned sh[];
    unsigned (*Ks0)[FL_STRIDE] = (unsigned (*)[FL_STRIDE])(sh);
    unsigned (*Vs0)[FL_STRIDE] = (unsigned (*)[FL_STRIDE])(sh + TILE_WORDS);
    unsigned (*Ks1)[FL_STRIDE] = (unsigned (*)[FL_STRIDE])(sh + 2 * TILE_WORDS);
    unsigned (*Vs1)[FL_STRIDE] = (unsigned (*)[FL_STRIDE])(sh + 3 * TILE_WORDS);

    const int tid  = threadIdx.x;
    const int w    = tid >> 5;
    const int lane = tid & 31;
    const int gid  = lane >> 2;
    const int tig  = lane & 3;
    const int bh   = blockIdx.y;            // b*16+h
    const int q0   = blockIdx.x * BQ;
    const int mq   = w * 16;

    const float* Qp = Q  + (size_t)bh * SEQ * HD;
    const float* Kp = K  + (size_t)bh * SEQ * HD;
    const float* Vp = Vt + (size_t)bh * HD * SEQ;

    const int ldr = tid >> 4;               // 0..7
    const int ldc = (tid & 15) * 4;         // word offset 0..60

    // ---- Stage Q through smem (buffer 0), pull fragments into registers.
    // Scale = 1/sqrt(Dh) * log2(e) so softmax runs in base 2.
    const float QSC = 0.125f * 1.44269504088896340736f;
#pragma unroll
    for (int it = 0; it < 8; it++) {
        int r = ldr + it * 8;
        float4 v = *reinterpret_cast<const float4*>(&Qp[(size_t)(q0 + r) * HD + ldc]);
        v.x *= QSC; v.y *= QSC; v.z *= QSC; v.w *= QSC;
        *reinterpret_cast<uint4*>(&Ks0[r][ldc]) = tf4(v);
    }
    __syncthreads();
    unsigned qa[8][4];
#pragma unroll
    for (int kk = 0; kk < 8; kk++) {
        qa[kk][0] = Ks0[mq + gid    ][kk * 8 + tig    ];
        qa[kk][1] = Ks0[mq + gid + 8][kk * 8 + tig    ];
        qa[kk][2] = Ks0[mq + gid    ][kk * 8 + tig + 4];
        qa[kk][3] = Ks0[mq + gid + 8][kk * 8 + tig + 4];
    }
    __syncthreads();

    // ---- Prologue: tile 0 into buffer 0
#pragma unroll
    for (int it = 0; it < 8; it++) {
        int r = ldr + it * 8;
        float4 kv = *reinterpret_cast<const float4*>(&Kp[(size_t)r * HD + ldc]);
        *reinterpret_cast<uint4*>(&Ks0[r][ldc]) = tf4(kv);
        float4 vv = *reinterpret_cast<const float4*>(&Vp[(size_t)r * SEQ + ldc]);
        *reinterpret_cast<uint4*>(&Vs0[r][ldc]) = tf4(vv);
    }
    __syncthreads();

    float o[8][4];
#pragma unroll
    for (int j = 0; j < 8; j++)
#pragma unroll
        for (int r = 0; r < 4; r++) o[j][r] = 0.f;
    float mrow[2] = {-1e30f, -1e30f};
    float lrow[2] = {0.f, 0.f};

    const int l0 = (lane & 28) | (tig >> 1);   // shuffle src for cols tig
    const bool odd = (tig & 1);

    for (int kb = 0; kb < SEQ / BKV; kb++) {
        unsigned (*Kc)[FL_STRIDE] = (kb & 1) ? Ks1 : Ks0;
        unsigned (*Vc)[FL_STRIDE] = (kb & 1) ? Vs1 : Vs0;
        unsigned (*Kn)[FL_STRIDE] = (kb & 1) ? Ks0 : Ks1;
        unsigned (*Vn)[FL_STRIDE] = (kb & 1) ? Vs0 : Vs1;
        const bool has_next = (kb + 1) < (SEQ / BKV);
        const int sN = (kb + 1) * BKV;

        float4 ld[8];
        if (has_next) {                       // prefetch next K behind S-matmul
#pragma unroll
            for (int it = 0; it < 8; it++) {
                int r = ldr + it * 8;
                ld[it] = *reinterpret_cast<const float4*>(&Kp[(size_t)(sN + r) * HD + ldc]);
            }
        }

        // S = (Q*scale) @ K^T : 16 x 64 per warp (Q frags from registers)
        float s[8][4];
#pragma unroll
        for (int j = 0; j < 8; j++)
#pragma unroll
            for (int r = 0; r < 4; r++) s[j][r] = 0.f;
#pragma unroll
        for (int kk = 0; kk < 8; kk++) {
#pragma unroll
            for (int j = 0; j < 8; j++) {
                unsigned b[2] = { Kc[j * 8 + gid][kk * 8 + tig],
                                  Kc[j * 8 + gid][kk * 8 + tig + 4] };
                mma8(s[j], qa[kk], b);
            }
        }

        if (has_next) {                       // commit K, prefetch V behind softmax+PV
#pragma unroll
            for (int it = 0; it < 8; it++) {
                int r = ldr + it * 8;
                *reinterpret_cast<uint4*>(&Kn[r][ldc]) = tf4(ld[it]);
                ld[it] = *reinterpret_cast<const float4*>(&Vp[(size_t)r * SEQ + sN + ldc]);
            }
        }

        // Online softmax (base 2); thread owns rows gid (regs 0,1) / gid+8 (2,3)
#pragma unroll
        for (int rr = 0; rr < 2; rr++) {
            float mx = -1e30f;
#pragma unroll
            for (int j = 0; j < 8; j++) {
                mx = fmaxf(mx, s[j][rr * 2]);
                mx = fmaxf(mx, s[j][rr * 2 + 1]);
            }
            mx = fmaxf(mx, __shfl_xor_sync(0xffffffffu, mx, 1));
            mx = fmaxf(mx, __shfl_xor_sync(0xffffffffu, mx, 2));
            float mnew = fmaxf(mrow[rr], mx);
            float corr = ex2(mrow[rr] - mnew);
            float rs = 0.f;
#pragma unroll
            for (int j = 0; j < 8; j++) {
                float e0 = ex2(s[j][rr * 2]     - mnew);
                float e1 = ex2(s[j][rr * 2 + 1] - mnew);
                s[j][rr * 2] = e0; s[j][rr * 2 + 1] = e1;
                rs += e0 + e1;
            }
            rs += __shfl_xor_sync(0xffffffffu, rs, 1);
            rs += __shfl_xor_sync(0xffffffffu, rs, 2);
            lrow[rr] = lrow[rr] * corr + rs;
            mrow[rr] = mnew;
#pragma unroll
            for (int j = 0; j < 8; j++) {
                o[j][rr * 2]     *= corr;
                o[j][rr * 2 + 1] *= corr;
            }
        }

        // O += P @ V : P C-frag -> A-frag entirely via shuffles (no smem)
#pragma unroll
        for (int j = 0; j < 8; j++) {
            unsigned v0 = f2tf(s[j][0]), v1 = f2tf(s[j][1]);
            unsigned v2 = f2tf(s[j][2]), v3 = f2tf(s[j][3]);
            unsigned t00 = __shfl_sync(0xffffffffu, v0, l0);
            unsigned t01 = __shfl_sync(0xffffffffu, v1, l0);
            unsigned t02 = __shfl_sync(0xffffffffu, v2, l0);
            unsigned t03 = __shfl_sync(0xffffffffu, v3, l0);
            unsigned t10 = __shfl_sync(0xffffffffu, v0, l0 + 2);
            unsigned t11 = __shfl_sync(0xffffffffu, v1, l0 + 2);
            unsigned t12 = __shfl_sync(0xffffffffu, v2, l0 + 2);
            unsigned t13 = __shfl_sync(0xffffffffu, v3, l0 + 2);
            unsigned a[4];
            a[0] = odd ? t01 : t00;   // P[gid  ][j*8+tig]
            a[1] = odd ? t03 : t02;   // P[gid+8][j*8+tig]
            a[2] = odd ? t11 : t10;   // P[gid  ][j*8+tig+4]
            a[3] = odd ? t13 : t12;   // P[gid+8][j*8+tig+4]
#pragma unroll
            for (int jj = 0; jj < 8; jj++) {
                unsigned b[2] = { Vc[jj * 8 + gid][j * 8 + tig],
                                  Vc[jj * 8 + gid][j * 8 + tig + 4] };
                mma8(o[jj], a, b);
            }
        }

        if (has_next) {                       // commit V
#pragma unroll
            for (int it = 0; it < 8; it++) {
                int r = ldr + it * 8;
                *reinterpret_cast<uint4*>(&Vn[r][ldc]) = tf4(ld[it]);
            }
        }
        __syncthreads();                      // single barrier per kv block
    }

    // Epilogue: O /= l, write concat layout [B*S, E] at column h*64+d
    const int b = bh >> 4, h = bh & 15;
    const float inv0 = 1.f / lrow[0];
    const float inv1 = 1.f / lrow[1];
    const int row0 = q0 + mq + gid;
    const int row1 = row0 + 8;
#pragma unroll
    for (int jj = 0; jj < 8; jj++) {
        int col = h * HD + jj * 8 + 2 * tig;
        outA[(size_t)(b * SEQ + row0) * EMBED + col    ] = o[jj][0] * inv0;
        outA[(size_t)(b * SEQ + row0) * EMBED + col + 1] = o[jj][1] * inv0;
        outA[(size_t)(b * SEQ + row1) * EMBED + col    ] = o[jj][2] * inv1;
        outA[(size_t)(b * SEQ + row1) * EMBED + col + 1] = o[jj][3] * inv1;
    }
}

// ---------------------------------------------------------------------------
// Launch
// ---------------------------------------------------------------------------
extern "C" void kernel_launch(void* const* d_in, const int* in_sizes, int n_in,
                              void* d_out, int out_size)
{
    const float* X  = (const float*)d_in[0];
    const float* Wq = (const float*)d_in[1];
    const float* bq = (const float*)d_in[2];
    const float* Wk = (const float*)d_in[3];
    const float* bk = (const float*)d_in[4];
    const float* Wv = (const float*)d_in[5];
    const float* bv = (const float*)d_in[6];
    const float* Wo = (const float*)d_in[7];
    const float* bo = (const float*)d_in[8];
    float* out = (float*)d_out;

    float *qb, *kb, *vtb, *ab;
    cudaGetSymbolAddress((void**)&qb,  g_Q);
    cudaGetSymbolAddress((void**)&kb,  g_K);
    cudaGetSymbolAddress((void**)&vtb, g_Vt);
    cudaGetSymbolAddress((void**)&ab,  g_A);

    cudaFuncSetAttribute(flash_attn, cudaFuncAttributeMaxDynamicSharedMemorySize,
                         FLASH_SMEM_BYTES);

    dim3 qkvgrid(EMBED / BN, MROWS / BM, 3);   // (8, 32, 3) fused QKV
    gemm_qkv<<<qkvgrid, 256>>>(X, Wq, bq, qb, Wk, bk, kb, Wv, bv, vtb);

    dim3 fgrid(SEQ / BQ, BATCH * HEADS);       // (32, 32)
    flash_attn<<<fgrid, 128, FLASH_SMEM_BYTES>>>(qb, kb, vtb, ab);

    dim3 ggrid(EMBED / BN, MROWS / BM);        // (8, 32)
    gemm_tf32<<<ggrid, 256>>>(ab, Wo, bo, out, 3);
}

// round 7
// speedup vs baseline: 1.1903x; 1.0004x over previous
#include <cuda_runtime.h>
#include <math.h>

#define EMBED 1024
#define HEADS 16
#define HD    64
#define BATCH 2
#define SEQ   2048
#define MROWS (BATCH*SEQ)   /* 4096 */

// ---------------------------------------------------------------------------
// Scratch (device globals: allocation-free per harness rules)
// ---------------------------------------------------------------------------
__device__ float g_Q [BATCH*HEADS*SEQ*HD];   // [B,H,S,Dh]
__device__ float g_K [BATCH*HEADS*SEQ*HD];   // [B,H,S,Dh]
__device__ float g_Vt[BATCH*HEADS*HD*SEQ];   // [B,H,Dh,S]  (V transposed)
__device__ float g_A [MROWS*EMBED];          // attention output, [B*S, E]

// ---------------------------------------------------------------------------
// TF32 helpers
// ---------------------------------------------------------------------------
__device__ __forceinline__ unsigned f2tf(float f) {
    unsigned u; asm("cvt.rna.tf32.f32 %0, %1;" : "=r"(u) : "f"(f)); return u;
}
__device__ __forceinline__ uint4 tf4(float4 v) {
    uint4 u; u.x = f2tf(v.x); u.y = f2tf(v.y); u.z = f2tf(v.z); u.w = f2tf(v.w);
    return u;
}
__device__ __forceinline__ float ex2(float x) {
    float y; asm("ex2.approx.f32 %0, %1;" : "=f"(y) : "f"(x)); return y;
}
// D(16x8,f32) += A(16x8,tf32,row) * B(8x8,tf32,col)
__device__ __forceinline__ void mma8(float* c, const unsigned* a, const unsigned* b) {
    asm volatile(
        "mma.sync.aligned.m16n8k8.row.col.f32.tf32.tf32.f32 "
        "{%0,%1,%2,%3},{%4,%5,%6,%7},{%8,%9},{%0,%1,%2,%3};\n"
        : "+f"(c[0]), "+f"(c[1]), "+f"(c[2]), "+f"(c[3])
        : "r"(a[0]), "r"(a[1]), "r"(a[2]), "r"(a[3]), "r"(b[0]), "r"(b[1]));
}

// Fragment layouts (gid = lane>>2, tig = lane&3):
//   A: a0(m=gid,  k=tig)  a1(m=gid+8, k=tig)  a2(m=gid, k=tig+4)  a3(m=gid+8, k=tig+4)
//   B: b0(k=tig,  n=gid)  b1(k=tig+4, n=gid)
//   C: c0(m=gid, n=2tig)  c1(m=gid, n=2tig+1) c2(m=gid+8, n=2tig) c3(m=gid+8, n=2tig+1)

// ---------------------------------------------------------------------------
// GEMM body: C[M=4096, N=1024] = A[4096,1024] @ W[1024,1024] + bias
// Block tile 128x128x32; 8 warps (2x4), warp tile 64x32.
// mode 0: write [B,H,S,Dh]; mode 2: write [B,H,Dh,S]; mode 3: row-major [M,N]
// ---------------------------------------------------------------------------
#define BM 128
#define BN 128
#define BK 32

__device__ __forceinline__ void
gemm_body(const float* __restrict__ A, const float* __restrict__ W,
          const float* __restrict__ bias, float* __restrict__ out, int mode)
{
    __shared__ __align__(16) unsigned As[BM][BK + 4];   // [m][k]
    __shared__ __align__(16) unsigned Bs[BK][BN + 4];   // [k][n]

    const int tid  = threadIdx.x;
    const int w    = tid >> 5;
    const int lane = tid & 31;
    const int gid  = lane >> 2;
    const int tig  = lane & 3;
    const int wm   = w >> 2;            // 0..1
    const int wn   = w & 3;             // 0..3
    const int m0   = blockIdx.y * BM;
    const int n0   = blockIdx.x * BN;

    float acc[4][4][4];
#pragma unroll
    for (int i = 0; i < 4; i++)
#pragma unroll
        for (int j = 0; j < 4; j++)
#pragma unroll
            for (int r = 0; r < 4; r++) acc[i][j][r] = 0.f;

    for (int k0 = 0; k0 < EMBED; k0 += BK) {
#pragma unroll
        for (int it = 0; it < 4; it++) {
            int idx = tid + it * 256;            // 0..1023
            int r = idx >> 3, c4 = idx & 7;
            float4 v = *reinterpret_cast<const float4*>(
                &A[(size_t)(m0 + r) * EMBED + k0 + c4 * 4]);
            *reinterpret_cast<uint4*>(&As[r][c4 * 4]) = tf4(v);
        }
#pragma unroll
        for (int it = 0; it < 4; it++) {
            int idx = tid + it * 256;
            int r = idx >> 5, c4 = idx & 31;
            float4 v = *reinterpret_cast<const float4*>(
                &W[(size_t)(k0 + r) * EMBED + n0 + c4 * 4]);
            *reinterpret_cast<uint4*>(&Bs[r][c4 * 4]) = tf4(v);
        }
        __syncthreads();

#pragma unroll
        for (int kk = 0; kk < BK; kk += 8) {
            unsigned af[4][4], bf[4][2];
#pragma unroll
            for (int i = 0; i < 4; i++) {
                int mb = wm * 64 + i * 16;
                af[i][0] = As[mb + gid    ][kk + tig    ];
                af[i][1] = As[mb + gid + 8][kk + tig    ];
                af[i][2] = As[mb + gid    ][kk + tig + 4];
                af[i][3] = As[mb + gid + 8][kk + tig + 4];
            }
#pragma unroll
            for (int j = 0; j < 4; j++) {
                int nb = wn * 32 + j * 8;
                bf[j][0] = Bs[kk + tig    ][nb + gid];
                bf[j][1] = Bs[kk + tig + 4][nb + gid];
            }
#pragma unroll
            for (int i = 0; i < 4; i++)
#pragma unroll
                for (int j = 0; j < 4; j++)
                    mma8(acc[i][j], af[i], bf[j]);
        }
        __syncthreads();
    }

#pragma unroll
    for (int i = 0; i < 4; i++) {
#pragma unroll
        for (int j = 0; j < 4; j++) {
#pragma unroll
            for (int r = 0; r < 4; r++) {
                int m = m0 + wm * 64 + i * 16 + gid + ((r >> 1) << 3);
                int n = n0 + wn * 32 + j * 8 + 2 * tig + (r & 1);
                float v = acc[i][j][r] + bias[n];
                if (mode == 3) {
                    out[(size_t)m * EMBED + n] = v;
                } else {
                    int b = m >> 11, s = m & (SEQ - 1);
                    int h = n >> 6,  d = n & (HD - 1);
                    if (mode == 2)
                        out[(((size_t)(b * HEADS + h)) * HD + d) * SEQ + s] = v;
                    else
                        out[(((size_t)(b * HEADS + h)) * SEQ + s) * HD + d] = v;
                }
            }
        }
    }
}

// Fused QKV: blockIdx.z selects the weight/output triple. 768 CTAs in one
// launch fills the chip (3 x 256-CTA launches each under-filled 296 slots).
__global__ void __launch_bounds__(256, 2)
gemm_qkv(const float* __restrict__ X,
         const float* __restrict__ Wq, const float* __restrict__ bq, float* __restrict__ Qo,
         const float* __restrict__ Wk, const float* __restrict__ bk, float* __restrict__ Ko,
         const float* __restrict__ Wv, const float* __restrict__ bv, float* __restrict__ Vo)
{
    if (blockIdx.z == 0)      gemm_body(X, Wq, bq, Qo, 0);
    else if (blockIdx.z == 1) gemm_body(X, Wk, bk, Ko, 0);
    else                      gemm_body(X, Wv, bv, Vo, 2);
}

__global__ void __launch_bounds__(256, 2)
gemm_tf32(const float* __restrict__ A, const float* __restrict__ W,
          const float* __restrict__ bias, float* __restrict__ out, int mode)
{
    gemm_body(A, W, bias, out, mode);
}

// ---------------------------------------------------------------------------
// Flash attention v2:
//  - BQ=64 q-rows, 4 warps (warp = 16 q-rows x 64 kv)
//  - Q fragments held in registers for the whole kv loop (no Q LDS in loop)
//  - P C-frag -> A-frag via warp shuffles (no Ps smem, no syncwarp)
//  - base-2 softmax (log2e folded into Q scale; raw ex2.approx)
//  - double-buffered K/V tiles, next-tile LDG prefetched into registers
//    behind the mma phases; ONE __syncthreads per kv block
//  - smem 68 KB x occ 3 (reg-limited), vs 104 KB x occ 1 before
// ---------------------------------------------------------------------------
#define BQ  64
#define BKV 64
#define FL_STRIDE 68                       // 64 + 4 pad, conflict-free frags
#define TILE_WORDS (BKV * FL_STRIDE)       // 4352
#define FLASH_SMEM_WORDS (4 * TILE_WORDS)  // K0 V0 K1 V1
#define FLASH_SMEM_BYTES (FLASH_SMEM_WORDS * 4)   /* 69632 */

__global__ void __launch_bounds__(128, 3)
flash_attn(const float* __restrict__ Q, const float* __restrict__ K,
           const float* __restrict__ Vt, float* __restrict__ outA)
{
    extern __shared__ unsigned sh[];
    unsigned (*Ks0)[FL_STRIDE] = (unsigned (*)[FL_STRIDE])(sh);
    unsigned (*Vs0)[FL_STRIDE] = (unsigned (*)[FL_STRIDE])(sh + TILE_WORDS);
    unsigned (*Ks1)[FL_STRIDE] = (unsigned (*)[FL_STRIDE])(sh + 2 * TILE_WORDS);
    unsigned (*Vs1)[FL_STRIDE] = (unsigned (*)[FL_STRIDE])(sh + 3 * TILE_WORDS);

    const int tid  = threadIdx.x;
    const int w    = tid >> 5;
    const int lane = tid & 31;
    const int gid  = lane >> 2;
    const int tig  = lane & 3;
    const int bh   = blockIdx.y;            // b*16+h
    const int q0   = blockIdx.x * BQ;
    const int mq   = w * 16;

    const float* Qp = Q  + (size_t)bh * SEQ * HD;
    const float* Kp = K  + (size_t)bh * SEQ * HD;
    const float* Vp = Vt + (size_t)bh * HD * SEQ;

    const int ldr = tid >> 4;               // 0..7
    const int ldc = (tid & 15) * 4;         // word offset 0..60

    // ---- Stage Q through smem (buffer 0), pull fragments into registers.
    // Scale = 1/sqrt(Dh) * log2(e) so softmax runs in base 2.
    const float QSC = 0.125f * 1.44269504088896340736f;
#pragma unroll
    for (int it = 0; it < 8; it++) {
        int r = ldr + it * 8;
        float4 v = *reinterpret_cast<const float4*>(&Qp[(size_t)(q0 + r) * HD + ldc]);
        v.x *= QSC; v.y *= QSC; v.z *= QSC; v.w *= QSC;
        *reinterpret_cast<uint4*>(&Ks0[r][ldc]) = tf4(v);
    }
    __syncthreads();
    unsigned qa[8][4];
#pragma unroll
    for (int kk = 0; kk < 8; kk++) {
        qa[kk][0] = Ks0[mq + gid    ][kk * 8 + tig    ];
        qa[kk][1] = Ks0[mq + gid + 8][kk * 8 + tig    ];
        qa[kk][2] = Ks0[mq + gid    ][kk * 8 + tig + 4];
        qa[kk][3] = Ks0[mq + gid + 8][kk * 8 + tig + 4];
    }
    __syncthreads();

    // ---- Prologue: tile 0 into buffer 0
#pragma unroll
    for (int it = 0; it < 8; it++) {
        int r = ldr + it * 8;
        float4 kv = *reinterpret_cast<const float4*>(&Kp[(size_t)r * HD + ldc]);
        *reinterpret_cast<uint4*>(&Ks0[r][ldc]) = tf4(kv);
        float4 vv = *reinterpret_cast<const float4*>(&Vp[(size_t)r * SEQ + ldc]);
        *reinterpret_cast<uint4*>(&Vs0[r][ldc]) = tf4(vv);
    }
    __syncthreads();

    float o[8][4];
#pragma unroll
    for (int j = 0; j < 8; j++)
#pragma unroll
        for (int r = 0; r < 4; r++) o[j][r] = 0.f;
    float mrow[2] = {-1e30f, -1e30f};
    float lrow[2] = {0.f, 0.f};

    const int l0 = (lane & 28) | (tig >> 1);   // shuffle src for cols tig
    const bool odd = (tig & 1);

    for (int kb = 0; kb < SEQ / BKV; kb++) {
        unsigned (*Kc)[FL_STRIDE] = (kb & 1) ? Ks1 : Ks0;
        unsigned (*Vc)[FL_STRIDE] = (kb & 1) ? Vs1 : Vs0;
        unsigned (*Kn)[FL_STRIDE] = (kb & 1) ? Ks0 : Ks1;
        unsigned (*Vn)[FL_STRIDE] = (kb & 1) ? Vs0 : Vs1;
        const bool has_next = (kb + 1) < (SEQ / BKV);
        const int sN = (kb + 1) * BKV;

        float4 ld[8];
        if (has_next) {                       // prefetch next K behind S-matmul
#pragma unroll
            for (int it = 0; it < 8; it++) {
                int r = ldr + it * 8;
                ld[it] = *reinterpret_cast<const float4*>(&Kp[(size_t)(sN + r) * HD + ldc]);
            }
        }

        // S = (Q*scale) @ K^T : 16 x 64 per warp (Q frags from registers)
        float s[8][4];
#pragma unroll
        for (int j = 0; j < 8; j++)
#pragma unroll
            for (int r = 0; r < 4; r++) s[j][r] = 0.f;
#pragma unroll
        for (int kk = 0; kk < 8; kk++) {
#pragma unroll
            for (int j = 0; j < 8; j++) {
                unsigned b[2] = { Kc[j * 8 + gid][kk * 8 + tig],
                                  Kc[j * 8 + gid][kk * 8 + tig + 4] };
                mma8(s[j], qa[kk], b);
            }
        }

        if (has_next) {                       // commit K, prefetch V behind softmax+PV
#pragma unroll
            for (int it = 0; it < 8; it++) {
                int r = ldr + it * 8;
                *reinterpret_cast<uint4*>(&Kn[r][ldc]) = tf4(ld[it]);
                ld[it] = *reinterpret_cast<const float4*>(&Vp[(size_t)r * SEQ + sN + ldc]);
            }
        }

        // Online softmax (base 2); thread owns rows gid (regs 0,1) / gid+8 (2,3)
#pragma unroll
        for (int rr = 0; rr < 2; rr++) {
            float mx = -1e30f;
#pragma unroll
            for (int j = 0; j < 8; j++) {
                mx = fmaxf(mx, s[j][rr * 2]);
                mx = fmaxf(mx, s[j][rr * 2 + 1]);
            }
            mx = fmaxf(mx, __shfl_xor_sync(0xffffffffu, mx, 1));
            mx = fmaxf(mx, __shfl_xor_sync(0xffffffffu, mx, 2));
            float mnew = fmaxf(mrow[rr], mx);
            float corr = ex2(mrow[rr] - mnew);
            float rs = 0.f;
#pragma unroll
            for (int j = 0; j < 8; j++) {
                float e0 = ex2(s[j][rr * 2]     - mnew);
                float e1 = ex2(s[j][rr * 2 + 1] - mnew);
                s[j][rr * 2] = e0; s[j][rr * 2 + 1] = e1;
                rs += e0 + e1;
            }
            rs += __shfl_xor_sync(0xffffffffu, rs, 1);
            rs += __shfl_xor_sync(0xffffffffu, rs, 2);
            lrow[rr] = lrow[rr] * corr + rs;
            mrow[rr] = mnew;
#pragma unroll
            for (int j = 0; j < 8; j++) {
                o[j][rr * 2]     *= corr;
                o[j][rr * 2 + 1] *= corr;
            }
        }

        // O += P @ V : P C-frag -> A-frag entirely via shuffles (no smem)
#pragma unroll
        for (int j = 0; j < 8; j++) {
            unsigned v0 = f2tf(s[j][0]), v1 = f2tf(s[j][1]);
            unsigned v2 = f2tf(s[j][2]), v3 = f2tf(s[j][3]);
            unsigned t00 = __shfl_sync(0xffffffffu, v0, l0);
            unsigned t01 = __shfl_sync(0xffffffffu, v1, l0);
            unsigned t02 = __shfl_sync(0xffffffffu, v2, l0);
            unsigned t03 = __shfl_sync(0xffffffffu, v3, l0);
            unsigned t10 = __shfl_sync(0xffffffffu, v0, l0 + 2);
            unsigned t11 = __shfl_sync(0xffffffffu, v1, l0 + 2);
            unsigned t12 = __shfl_sync(0xffffffffu, v2, l0 + 2);
            unsigned t13 = __shfl_sync(0xffffffffu, v3, l0 + 2);
            unsigned a[4];
            a[0] = odd ? t01 : t00;   // P[gid  ][j*8+tig]
            a[1] = odd ? t03 : t02;   // P[gid+8][j*8+tig]
            a[2] = odd ? t11 : t10;   // P[gid  ][j*8+tig+4]
            a[3] = odd ? t13 : t12;   // P[gid+8][j*8+tig+4]
#pragma unroll
            for (int jj = 0; jj < 8; jj++) {
                unsigned b[2] = { Vc[jj * 8 + gid][j * 8 + tig],
                                  Vc[jj * 8 + gid][j * 8 + tig + 4] };
                mma8(o[jj], a, b);
            }
        }

        if (has_next) {                       // commit V
#pragma unroll
            for (int it = 0; it < 8; it++) {
                int r = ldr + it * 8;
                *reinterpret_cast<uint4*>(&Vn[r][ldc]) = tf4(ld[it]);
            }
        }
        __syncthreads();                      // single barrier per kv block
    }

    // Epilogue: O /= l, write concat layout [B*S, E] at column h*64+d
    const int b = bh >> 4, h = bh & 15;
    const float inv0 = 1.f / lrow[0];
    const float inv1 = 1.f / lrow[1];
    const int row0 = q0 + mq + gid;
    const int row1 = row0 + 8;
#pragma unroll
    for (int jj = 0; jj < 8; jj++) {
        int col = h * HD + jj * 8 + 2 * tig;
        outA[(size_t)(b * SEQ + row0) * EMBED + col    ] = o[jj][0] * inv0;
        outA[(size_t)(b * SEQ + row0) * EMBED + col + 1] = o[jj][1] * inv0;
        outA[(size_t)(b * SEQ + row1) * EMBED + col    ] = o[jj][2] * inv1;
        outA[(size_t)(b * SEQ + row1) * EMBED + col + 1] = o[jj][3] * inv1;
    }
}

// ---------------------------------------------------------------------------
// Launch
// ---------------------------------------------------------------------------
extern "C" void kernel_launch(void* const* d_in, const int* in_sizes, int n_in,
                              void* d_out, int out_size)
{
    const float* X  = (const float*)d_in[0];
    const float* Wq = (const float*)d_in[1];
    const float* bq = (const float*)d_in[2];
    const float* Wk = (const float*)d_in[3];
    const float* bk = (const float*)d_in[4];
    const float* Wv = (const float*)d_in[5];
    const float* bv = (const float*)d_in[6];
    const float* Wo = (const float*)d_in[7];
    const float* bo = (const float*)d_in[8];
    float* out = (float*)d_out;

    float *qb, *kb, *vtb, *ab;
    cudaGetSymbolAddress((void**)&qb,  g_Q);
    cudaGetSymbolAddress((void**)&kb,  g_K);
    cudaGetSymbolAddress((void**)&vtb, g_Vt);
    cudaGetSymbolAddress((void**)&ab,  g_A);

    cudaFuncSetAttribute(flash_attn, cudaFuncAttributeMaxDynamicSharedMemorySize,
                         FLASH_SMEM_BYTES);

    dim3 qkvgrid(EMBED / BN, MROWS / BM, 3);   // (8, 32, 3) fused QKV
    gemm_qkv<<<qkvgrid, 256>>>(X, Wq, bq, qb, Wk, bk, kb, Wv, bv, vtb);

    dim3 fgrid(SEQ / BQ, BATCH * HEADS);       // (32, 32)
    flash_attn<<<fgrid, 128, FLASH_SMEM_BYTES>>>(qb, kb, vtb, ab);

    dim3 ggrid(EMBED / BN, MROWS / BM);        // (8, 32)
    gemm_tf32<<<ggrid, 256>>>(ab, Wo, bo, out, 3);
}

// round 11
// speedup vs baseline: 1.1920x; 1.0014x over previous
#include <cuda_runtime.h>
#include <cstdint>
#include <math.h>

#define EMBED 1024
#define HEADS 16
#define HD    64
#define BATCH 2
#define SEQ   2048
#define MROWS (BATCH*SEQ)   /* 4096 */

// ---------------------------------------------------------------------------
// Scratch (device globals: allocation-free per harness rules)
// ---------------------------------------------------------------------------
__device__ float g_Q [BATCH*HEADS*SEQ*HD];   // [B,H,S,Dh]
__device__ float g_K [BATCH*HEADS*SEQ*HD];   // [B,H,S,Dh]
__device__ float g_Vt[BATCH*HEADS*HD*SEQ];   // [B,H,Dh,S]  (V transposed)
__device__ float g_A [MROWS*EMBED];          // attention output (tf32-rounded)
__device__ float g_Xt[MROWS*EMBED];          // X, tf32-rounded
__device__ float g_Wt[4*EMBED*EMBED];        // Wq,Wk,Wv,Wo tf32-rounded [k][n]

// ---------------------------------------------------------------------------
// Helpers
// ---------------------------------------------------------------------------
__device__ __forceinline__ unsigned f2tf(float f) {
    unsigned u; asm("cvt.rna.tf32.f32 %0, %1;" : "=r"(u) : "f"(f)); return u;
}
__device__ __forceinline__ uint4 tf4(float4 v) {
    uint4 u; u.x = f2tf(v.x); u.y = f2tf(v.y); u.z = f2tf(v.z); u.w = f2tf(v.w);
    return u;
}
__device__ __forceinline__ float ex2(float x) {
    float y; asm("ex2.approx.f32 %0, %1;" : "=f"(y) : "f"(x)); return y;
}
__device__ __forceinline__ uint32_t smem_u32(const void* p) {
    uint32_t a;
    asm("{ .reg .u64 t; cvta.to.shared.u64 t, %1; cvt.u32.u64 %0, t; }" : "=r"(a) : "l"(p));
    return a;
}
// D(16x8,f32) += A(16x8,tf32,row) * B(8x8,tf32,col)
__device__ __forceinline__ void mma8(float* c, const unsigned* a, const unsigned* b) {
    asm volatile(
        "mma.sync.aligned.m16n8k8.row.col.f32.tf32.tf32.f32 "
        "{%0,%1,%2,%3},{%4,%5,%6,%7},{%8,%9},{%0,%1,%2,%3};\n"
        : "+f"(c[0]), "+f"(c[1]), "+f"(c[2]), "+f"(c[3])
        : "r"(a[0]), "r"(a[1]), "r"(a[2]), "r"(a[3]), "r"(b[0]), "r"(b[1]));
}

// cp.async (LDGSTS, sm_80+ — compiles under compute_103)
#define CP16(dst, src) \
    asm volatile("cp.async.cg.shared.global [%0], [%1], 16;" :: "r"(dst), "l"(src))
#define CP_COMMIT() asm volatile("cp.async.commit_group;" ::: "memory")
#define CP_WAIT0()  asm volatile("cp.async.wait_group 0;" ::: "memory")
#define CP_WAIT1()  asm volatile("cp.async.wait_group 1;" ::: "memory")

// ---------------------------------------------------------------------------
// Prep: tf32-round X and the four weight matrices (RNA — same rounding the
// old gemm applied at load time, so the math chain is unchanged).
// ---------------------------------------------------------------------------
__global__ void __launch_bounds__(256)
prep_round(const float* __restrict__ X,
           const float* __restrict__ Wq, const float* __restrict__ Wk,
           const float* __restrict__ Wv, const float* __restrict__ Wo,
           float* __restrict__ Xt, float* __restrict__ Wt)
{
    const size_t NX = (size_t)MROWS * EMBED / 4;   // 1M float4
    const size_t NW = (size_t)EMBED * EMBED / 4;   // 256K float4
    size_t i = (size_t)blockIdx.x * 256 + threadIdx.x;
    const float4* src; float4* dst; size_t o;
    if (i < NX) {
        src = (const float4*)X; dst = (float4*)Xt; o = i;
    } else {
        size_t r = i - NX;
        int ws = (int)(r / NW); o = r % NW;
        const float* W = (ws == 0) ? Wq : (ws == 1) ? Wk : (ws == 2) ? Wv : Wo;
        src = (const float4*)W;
        dst = (float4*)(Wt + (size_t)ws * EMBED * EMBED);
    }
    float4 v = src[o];
    uint4  u = tf4(v);
    dst[o] = *reinterpret_cast<float4*>(&u);
}

// ---------------------------------------------------------------------------
// Pipelined GEMM: C[4096,1024] = A @ W + bias, tile 128x128x32, 8 warps 2x4,
// 3-stage cp.async pipeline, ONE __syncthreads per k-tile.
// Inputs pre-rounded tf32 in gmem (cp.async is a byte copy).
// mode 0: write [B,H,S,Dh]; mode 2: [B,H,Dh,S]; mode 3: row-major [M,N].
// ---------------------------------------------------------------------------
#define BM 128
#define BN 128
#define BK 32
#define ASTR 36               /* A row stride (words): 144B, 16B-aligned, cf-free */
#define BSTR 132              /* B row stride (words): 528B */
#define A_BUF (BM*ASTR*4)     /* 18432 B */
#define B_BUF (BK*BSTR*4)     /* 16896 B */
#define NSTAGE 3
#define PIPE_SMEM (NSTAGE*A_BUF + NSTAGE*B_BUF)   /* 105984 B */
#define NKT (EMBED/BK)        /* 32 */

__device__ __forceinline__ void
gemm_pipe_body(const float* __restrict__ A, const float* __restrict__ W,
               const float* __restrict__ bias, float* __restrict__ out, int mode)
{
    extern __shared__ char sm[];
    const uint32_t sb = smem_u32(sm);
    const int t    = threadIdx.x;
    const int w    = t >> 5;
    const int lane = t & 31;
    const int gid  = lane >> 2;
    const int tig  = lane & 3;
    const int wm   = w >> 2;            // 0..1
    const int wn   = w & 3;             // 0..3
    const int m0   = blockIdx.y * BM;
    const int n0   = blockIdx.x * BN;

    uint32_t aoff[NSTAGE], boff[NSTAGE];
#pragma unroll
    for (int s = 0; s < NSTAGE; s++) {
        aoff[s] = sb + s * A_BUF;
        boff[s] = sb + NSTAGE * A_BUF + s * B_BUF;
    }

    auto issue = [&](int slot, int k0) {
#pragma unroll
        for (int it = 0; it < 4; it++) {         // A: 1024 chunks / 256 thr
            int idx = t + it * 256;
            int r = idx >> 3, c = idx & 7;
            CP16(aoff[slot] + r * (ASTR * 4) + c * 16,
                 A + (size_t)(m0 + r) * EMBED + k0 + c * 4);
        }
#pragma unroll
        for (int it = 0; it < 4; it++) {         // B: 1024 chunks
            int idx = t + it * 256;
            int r = idx >> 5, c = idx & 31;
            CP16(boff[slot] + r * (BSTR * 4) + c * 16,
                 W + (size_t)(k0 + r) * EMBED + n0 + c * 4);
        }
        CP_COMMIT();
    };

    float acc[4][4][4];
#pragma unroll
    for (int i = 0; i < 4; i++)
#pragma unroll
        for (int j = 0; j < 4; j++)
#pragma unroll
            for (int r = 0; r < 4; r++) acc[i][j][r] = 0.f;

    issue(0, 0);
    issue(1, BK);

    for (int kt = 0; kt < NKT; kt++) {
        const int slot = kt % NSTAGE;
        if (kt + 1 < NKT) { CP_WAIT1(); } else { CP_WAIT0(); }
        __syncthreads();
        if (kt + 2 < NKT) issue((kt + 2) % NSTAGE, (kt + 2) * BK);

        const unsigned (*As)[ASTR] = (const unsigned (*)[ASTR])(sm + (aoff[slot] - sb));
        const unsigned (*Bs)[BSTR] = (const unsigned (*)[BSTR])(sm + (boff[slot] - sb));

#pragma unroll
        for (int kk = 0; kk < BK; kk += 8) {
            unsigned af[4][4], bf[4][2];
#pragma unroll
            for (int i = 0; i < 4; i++) {
                int mb = wm * 64 + i * 16;
                af[i][0] = As[mb + gid    ][kk + tig    ];
                af[i][1] = As[mb + gid + 8][kk + tig    ];
                af[i][2] = As[mb + gid    ][kk + tig + 4];
                af[i][3] = As[mb + gid + 8][kk + tig + 4];
            }
#pragma unroll
            for (int j = 0; j < 4; j++) {
                int nb = wn * 32 + j * 8;
                bf[j][0] = Bs[kk + tig    ][nb + gid];
                bf[j][1] = Bs[kk + tig + 4][nb + gid];
            }
#pragma unroll
            for (int i = 0; i < 4; i++)
#pragma unroll
                for (int j = 0; j < 4; j++)
                    mma8(acc[i][j], af[i], bf[j]);
        }
        __syncthreads();     // all reads of this slot done before its reuse
    }

    // Epilogue (identical mapping to the R6-passing kernel)
#pragma unroll
    for (int i = 0; i < 4; i++) {
#pragma unroll
        for (int j = 0; j < 4; j++) {
#pragma unroll
            for (int r = 0; r < 4; r++) {
                int m = m0 + wm * 64 + i * 16 + gid + ((r >> 1) << 3);
                int n = n0 + wn * 32 + j * 8 + 2 * tig + (r & 1);
                float v = acc[i][j][r] + bias[n];
                if (mode == 3) {
                    out[(size_t)m * EMBED + n] = v;
                } else {
                    int b = m >> 11, s = m & (SEQ - 1);
                    int h = n >> 6,  d = n & (HD - 1);
                    if (mode == 2)
                        out[(((size_t)(b * HEADS + h)) * HD + d) * SEQ + s] = v;
                    else
                        out[(((size_t)(b * HEADS + h)) * SEQ + s) * HD + d] = v;
                }
            }
        }
    }
}

__global__ void __launch_bounds__(256, 2)
gemm_qkv(const float* __restrict__ Xt, const float* __restrict__ Wt,
         const float* __restrict__ bq, const float* __restrict__ bk,
         const float* __restrict__ bv,
         float* __restrict__ Qo, float* __restrict__ Ko, float* __restrict__ Vo)
{
    if (blockIdx.z == 0)
        gemm_pipe_body(Xt, Wt,                 bq, Qo, 0);
    else if (blockIdx.z == 1)
        gemm_pipe_body(Xt, Wt + EMBED*EMBED,   bk, Ko, 0);
    else
        gemm_pipe_body(Xt, Wt + 2*EMBED*EMBED, bv, Vo, 2);
}

__global__ void __launch_bounds__(256, 2)
gemm_out(const float* __restrict__ Aa, const float* __restrict__ Wt,
         const float* __restrict__ bias, float* __restrict__ out)
{
    gemm_pipe_body(Aa, Wt + 3*EMBED*EMBED, bias, out, 3);
}

// ---------------------------------------------------------------------------
// Flash attention (R6-passing version; only change: epilogue stores
// tf32-rounded values so the O-projection's cp.async path sees the same
// bits the old gemm produced by rounding at load time).
// ---------------------------------------------------------------------------
#define BQ  64
#define BKV 64
#define FL_STRIDE 68
#define TILE_WORDS (BKV * FL_STRIDE)
#define FLASH_SMEM_WORDS (4 * TILE_WORDS)
#define FLASH_SMEM_BYTES (FLASH_SMEM_WORDS * 4)   /* 69632 */

__global__ void __launch_bounds__(128, 3)
flash_attn(const float* __restrict__ Q, const float* __restrict__ K,
           const float* __restrict__ Vt, float* __restrict__ outA)
{
    extern __shared__ unsigned sh[];
    unsigned (*Ks0)[FL_STRIDE] = (unsigned (*)[FL_STRIDE])(sh);
    unsigned (*Vs0)[FL_STRIDE] = (unsigned (*)[FL_STRIDE])(sh + TILE_WORDS);
    unsigned (*Ks1)[FL_STRIDE] = (unsigned (*)[FL_STRIDE])(sh + 2 * TILE_WORDS);
    unsigned (*Vs1)[FL_STRIDE] = (unsigned (*)[FL_STRIDE])(sh + 3 * TILE_WORDS);

    const int tid  = threadIdx.x;
    const int w    = tid >> 5;
    const int lane = tid & 31;
    const int gid  = lane >> 2;
    const int tig  = lane & 3;
    const int bh   = blockIdx.y;
    const int q0   = blockIdx.x * BQ;
    const int mq   = w * 16;

    const float* Qp = Q  + (size_t)bh * SEQ * HD;
    const float* Kp = K  + (size_t)bh * SEQ * HD;
    const float* Vp = Vt + (size_t)bh * HD * SEQ;

    const int ldr = tid >> 4;
    const int ldc = (tid & 15) * 4;

    const float QSC = 0.125f * 1.44269504088896340736f;
#pragma unroll
    for (int it = 0; it < 8; it++) {
        int r = ldr + it * 8;
        float4 v = *reinterpret_cast<const float4*>(&Qp[(size_t)(q0 + r) * HD + ldc]);
        v.x *= QSC; v.y *= QSC; v.z *= QSC; v.w *= QSC;
        *reinterpret_cast<uint4*>(&Ks0[r][ldc]) = tf4(v);
    }
    __syncthreads();
    unsigned qa[8][4];
#pragma unroll
    for (int kk = 0; kk < 8; kk++) {
        qa[kk][0] = Ks0[mq + gid    ][kk * 8 + tig    ];
        qa[kk][1] = Ks0[mq + gid + 8][kk * 8 + tig    ];
        qa[kk][2] = Ks0[mq + gid    ][kk * 8 + tig + 4];
        qa[kk][3] = Ks0[mq + gid + 8][kk * 8 + tig + 4];
    }
    __syncthreads();

#pragma unroll
    for (int it = 0; it < 8; it++) {
        int r = ldr + it * 8;
        float4 kv = *reinterpret_cast<const float4*>(&Kp[(size_t)r * HD + ldc]);
        *reinterpret_cast<uint4*>(&Ks0[r][ldc]) = tf4(kv);
        float4 vv = *reinterpret_cast<const float4*>(&Vp[(size_t)r * SEQ + ldc]);
        *reinterpret_cast<uint4*>(&Vs0[r][ldc]) = tf4(vv);
    }
    __syncthreads();

    float o[8][4];
#pragma unroll
    for (int j = 0; j < 8; j++)
#pragma unroll
        for (int r = 0; r < 4; r++) o[j][r] = 0.f;
    float mrow[2] = {-1e30f, -1e30f};
    float lrow[2] = {0.f, 0.f};

    const int l0 = (lane & 28) | (tig >> 1);
    const bool odd = (tig & 1);

    for (int kb = 0; kb < SEQ / BKV; kb++) {
        unsigned (*Kc)[FL_STRIDE] = (kb & 1) ? Ks1 : Ks0;
        unsigned (*Vc)[FL_STRIDE] = (kb & 1) ? Vs1 : Vs0;
        unsigned (*Kn)[FL_STRIDE] = (kb & 1) ? Ks0 : Ks1;
        unsigned (*Vn)[FL_STRIDE] = (kb & 1) ? Vs0 : Vs1;
        const bool has_next = (kb + 1) < (SEQ / BKV);
        const int sN = (kb + 1) * BKV;

        float4 ld[8];
        if (has_next) {
#pragma unroll
            for (int it = 0; it < 8; it++) {
                int r = ldr + it * 8;
                ld[it] = *reinterpret_cast<const float4*>(&Kp[(size_t)(sN + r) * HD + ldc]);
            }
        }

        float s[8][4];
#pragma unroll
        for (int j = 0; j < 8; j++)
#pragma unroll
            for (int r = 0; r < 4; r++) s[j][r] = 0.f;
#pragma unroll
        for (int kk = 0; kk < 8; kk++) {
#pragma unroll
            for (int j = 0; j < 8; j++) {
                unsigned b[2] = { Kc[j * 8 + gid][kk * 8 + tig],
                                  Kc[j * 8 + gid][kk * 8 + tig + 4] };
                mma8(s[j], qa[kk], b);
            }
        }

        if (has_next) {
#pragma unroll
            for (int it = 0; it < 8; it++) {
                int r = ldr + it * 8;
                *reinterpret_cast<uint4*>(&Kn[r][ldc]) = tf4(ld[it]);
                ld[it] = *reinterpret_cast<const float4*>(&Vp[(size_t)r * SEQ + sN + ldc]);
            }
        }

#pragma unroll
        for (int rr = 0; rr < 2; rr++) {
            float mx = -1e30f;
#pragma unroll
            for (int j = 0; j < 8; j++) {
                mx = fmaxf(mx, s[j][rr * 2]);
                mx = fmaxf(mx, s[j][rr * 2 + 1]);
            }
            mx = fmaxf(mx, __shfl_xor_sync(0xffffffffu, mx, 1));
            mx = fmaxf(mx, __shfl_xor_sync(0xffffffffu, mx, 2));
            float mnew = fmaxf(mrow[rr], mx);
            float corr = ex2(mrow[rr] - mnew);
            float rs = 0.f;
#pragma unroll
            for (int j = 0; j < 8; j++) {
                float e0 = ex2(s[j][rr * 2]     - mnew);
                float e1 = ex2(s[j][rr * 2 + 1] - mnew);
                s[j][rr * 2] = e0; s[j][rr * 2 + 1] = e1;
                rs += e0 + e1;
            }
            rs += __shfl_xor_sync(0xffffffffu, rs, 1);
            rs += __shfl_xor_sync(0xffffffffu, rs, 2);
            lrow[rr] = lrow[rr] * corr + rs;
            mrow[rr] = mnew;
#pragma unroll
            for (int j = 0; j < 8; j++) {
                o[j][rr * 2]     *= corr;
                o[j][rr * 2 + 1] *= corr;
            }
        }

#pragma unroll
        for (int j = 0; j < 8; j++) {
            unsigned v0 = f2tf(s[j][0]), v1 = f2tf(s[j][1]);
            unsigned v2 = f2tf(s[j][2]), v3 = f2tf(s[j][3]);
            unsigned t00 = __shfl_sync(0xffffffffu, v0, l0);
            unsigned t01 = __shfl_sync(0xffffffffu, v1, l0);
            unsigned t02 = __shfl_sync(0xffffffffu, v2, l0);
            unsigned t03 = __shfl_sync(0xffffffffu, v3, l0);
            unsigned t10 = __shfl_sync(0xffffffffu, v0, l0 + 2);
            unsigned t11 = __shfl_sync(0xffffffffu, v1, l0 + 2);
            unsigned t12 = __shfl_sync(0xffffffffu, v2, l0 + 2);
            unsigned t13 = __shfl_sync(0xffffffffu, v3, l0 + 2);
            unsigned a[4];
            a[0] = odd ? t01 : t00;
            a[1] = odd ? t03 : t02;
            a[2] = odd ? t11 : t10;
            a[3] = odd ? t13 : t12;
#pragma unroll
            for (int jj = 0; jj < 8; jj++) {
                unsigned b[2] = { Vc[jj * 8 + gid][j * 8 + tig],
                                  Vc[jj * 8 + gid][j * 8 + tig + 4] };
                mma8(o[jj], a, b);
            }
        }

        if (has_next) {
#pragma unroll
            for (int it = 0; it < 8; it++) {
                int r = ldr + it * 8;
                *reinterpret_cast<uint4*>(&Vn[r][ldc]) = tf4(ld[it]);
            }
        }
        __syncthreads();
    }

    const int b = bh >> 4, h = bh & 15;
    const float inv0 = 1.f / lrow[0];
    const float inv1 = 1.f / lrow[1];
    const int row0 = q0 + mq + gid;
    const int row1 = row0 + 8;
#pragma unroll
    for (int jj = 0; jj < 8; jj++) {
        int col = h * HD + jj * 8 + 2 * tig;
        outA[(size_t)(b * SEQ + row0) * EMBED + col    ] =
            __uint_as_float(f2tf(o[jj][0] * inv0));
        outA[(size_t)(b * SEQ + row0) * EMBED + col + 1] =
            __uint_as_float(f2tf(o[jj][1] * inv0));
        outA[(size_t)(b * SEQ + row1) * EMBED + col    ] =
            __uint_as_float(f2tf(o[jj][2] * inv1));
        outA[(size_t)(b * SEQ + row1) * EMBED + col + 1] =
            __uint_as_float(f2tf(o[jj][3] * inv1));
    }
}

// ---------------------------------------------------------------------------
// Launch
// ---------------------------------------------------------------------------
extern "C" void kernel_launch(void* const* d_in, const int* in_sizes, int n_in,
                              void* d_out, int out_size)
{
    const float* X  = (const float*)d_in[0];
    const float* Wq = (const float*)d_in[1];
    const float* bq = (const float*)d_in[2];
    const float* Wk = (const float*)d_in[3];
    const float* bk = (const float*)d_in[4];
    const float* Wv = (const float*)d_in[5];
    const float* bv = (const float*)d_in[6];
    const float* Wo = (const float*)d_in[7];
    const float* bo = (const float*)d_in[8];
    float* out = (float*)d_out;

    float *qb, *kb, *vtb, *ab, *xtb, *wtb;
    cudaGetSymbolAddress((void**)&qb,  g_Q);
    cudaGetSymbolAddress((void**)&kb,  g_K);
    cudaGetSymbolAddress((void**)&vtb, g_Vt);
    cudaGetSymbolAddress((void**)&ab,  g_A);
    cudaGetSymbolAddress((void**)&xtb, g_Xt);
    cudaGetSymbolAddress((void**)&wtb, g_Wt);

    cudaFuncSetAttribute(flash_attn, cudaFuncAttributeMaxDynamicSharedMemorySize,
                         FLASH_SMEM_BYTES);
    cudaFuncSetAttribute(gemm_qkv, cudaFuncAttributeMaxDynamicSharedMemorySize,
                         PIPE_SMEM);
    cudaFuncSetAttribute(gemm_out, cudaFuncAttributeMaxDynamicSharedMemorySize,
                         PIPE_SMEM);

    // 1) tf32 pre-round X + weights (2M float4 chunks)
    prep_round<<<8192, 256>>>(X, Wq, Wk, Wv, Wo, xtb, wtb);

    // 2) fused QKV projections (pipelined)
    dim3 qkvgrid(EMBED / BN, MROWS / BM, 3);     // (8, 32, 3)
    gemm_qkv<<<qkvgrid, 256, PIPE_SMEM>>>(xtb, wtb, bq, bk, bv, qb, kb, vtb);

    // 3) attention
    dim3 fgrid(SEQ / BQ, BATCH * HEADS);         // (32, 32)
    flash_attn<<<fgrid, 128, FLASH_SMEM_BYTES>>>(qb, kb, vtb, ab);

    // 4) output projection (pipelined)
    dim3 ogrid(EMBED / BN, MROWS / BM);          // (8, 32)
    gemm_out<<<ogrid, 256, PIPE_SMEM>>>(ab, wtb, bo, out);
}

// round 12
// speedup vs baseline: 1.2800x; 1.0739x over previous
#include <cuda_runtime.h>
#include <cstdint>
#include <math.h>

#define EMBED 1024
#define HEADS 16
#define HD    64
#define BATCH 2
#define SEQ   2048
#define MROWS (BATCH*SEQ)   /* 4096 */

// ---------------------------------------------------------------------------
// Scratch (device globals: allocation-free per harness rules)
// ---------------------------------------------------------------------------
// Pair-permutation: within every 8-wide block of the contraction-ish dim,
// logical index i is stored at physical position (i<4 ? 2i : 2(i-4)+1).
// This makes mma.sync slot pairs (tig, tig+4) physically adjacent -> LDS.64.
__device__ float g_Q [BATCH*HEADS*SEQ*HD];   // [B,H,S,Dh], d pair-permuted
__device__ float g_K [BATCH*HEADS*SEQ*HD];   // [B,H,S,Dh], d pair-permuted
__device__ float g_Vt[BATCH*HEADS*HD*SEQ];   // [B,H,Dh,S], s pair-permuted
__device__ float g_A [MROWS*EMBED];          // attn out, tf32, k pair-permuted
__device__ float g_Xt[MROWS*EMBED];          // X tf32, k pair-permuted
__device__ float g_Wt[4*EMBED*EMBED];        // W^T [n][k] tf32, k pair-permuted

// ---------------------------------------------------------------------------
// Helpers
// ---------------------------------------------------------------------------
__device__ __forceinline__ unsigned f2tf(float f) {
    unsigned u; asm("cvt.rna.tf32.f32 %0, %1;" : "=r"(u) : "f"(f)); return u;
}
__device__ __forceinline__ uint4 tf4(float4 v) {
    uint4 u; u.x = f2tf(v.x); u.y = f2tf(v.y); u.z = f2tf(v.z); u.w = f2tf(v.w);
    return u;
}
__device__ __forceinline__ float ex2(float x) {
    float y; asm("ex2.approx.f32 %0, %1;" : "=f"(y) : "f"(x)); return y;
}
__device__ __forceinline__ int pp8(int i) {   // pair-perm within 8-block
    return (i < 4) ? 2 * i : 2 * (i - 4) + 1;
}
// D(16x8,f32) += A(16x8,tf32,row) * B(8x8,tf32,col)
__device__ __forceinline__ void mma8(float* c, const unsigned* a, const unsigned* b) {
    asm volatile(
        "mma.sync.aligned.m16n8k8.row.col.f32.tf32.tf32.f32 "
        "{%0,%1,%2,%3},{%4,%5,%6,%7},{%8,%9},{%0,%1,%2,%3};\n"
        : "+f"(c[0]), "+f"(c[1]), "+f"(c[2]), "+f"(c[3])
        : "r"(a[0]), "r"(a[1]), "r"(a[2]), "r"(a[3]), "r"(b[0]), "r"(b[1]));
}

// cp.async (sm_80 feature set — compiles under compute_103)
#define CP16(dst, src) \
    asm volatile("cp.async.cg.shared.global [%0], [%1], 16;" :: "r"(dst), "l"(src))
#define CP_COMMIT() asm volatile("cp.async.commit_group;" ::: "memory")
#define CP_WAIT0()  asm volatile("cp.async.wait_group 0;" ::: "memory")

__device__ __forceinline__ uint32_t smem_u32(const void* p) {
    uint32_t a;
    asm("{ .reg .u64 t; cvta.to.shared.u64 t, %1; cvt.u32.u64 %0, t; }" : "=r"(a) : "l"(p));
    return a;
}

// ---------------------------------------------------------------------------
// Prep: X -> tf32, k pair-permuted (same row layout).
// ---------------------------------------------------------------------------
__global__ void __launch_bounds__(256)
prep_x(const float* __restrict__ X, float* __restrict__ Xt)
{
    size_t i = (size_t)blockIdx.x * 256 + threadIdx.x;    // float4 index
    float4 v = reinterpret_cast<const float4*>(X)[i];
    uint4  u = tf4(v);
    size_t e = i * 4;
    size_t row = e >> 10;
    int k = (int)(e & 1023);
    // logical k..k+3 map to phys (k&~7)+off+{0,2,4,6}, off = (k&4)?1:0
    float* d = Xt + (row << 10) + (k & ~7) + ((k & 4) ? 1 : 0);
    d[0] = __uint_as_float(u.x);
    d[2] = __uint_as_float(u.y);
    d[4] = __uint_as_float(u.z);
    d[6] = __uint_as_float(u.w);
}

// Prep: W [k][n] -> Wt [n][k], tf32, k pair-permuted. 4 matrices via z.
__global__ void __launch_bounds__(256)
prep_w(const float* __restrict__ W0, const float* __restrict__ W1,
       const float* __restrict__ W2, const float* __restrict__ W3,
       float* __restrict__ Wt)
{
    __shared__ float s[32][33];
    const float* W = (blockIdx.z == 0) ? W0 : (blockIdx.z == 1) ? W1
                    : (blockIdx.z == 2) ? W2 : W3;
    float* o = Wt + (size_t)blockIdx.z * EMBED * EMBED;
    const int kx = blockIdx.y * 32, nx = blockIdx.x * 32;
    const int t = threadIdx.x, r = t >> 3, c = t & 7;

    float4 v = *reinterpret_cast<const float4*>(&W[(size_t)(kx + r) * EMBED + nx + c * 4]);
    int rp = (r & 24) | pp8(r & 7);          // permuted k slot
    s[c * 4 + 0][rp] = __uint_as_float(f2tf(v.x));
    s[c * 4 + 1][rp] = __uint_as_float(f2tf(v.y));
    s[c * 4 + 2][rp] = __uint_as_float(f2tf(v.z));
    s[c * 4 + 3][rp] = __uint_as_float(f2tf(v.w));
    __syncthreads();
    float4 u;
    u.x = s[r][c * 4 + 0]; u.y = s[r][c * 4 + 1];
    u.z = s[r][c * 4 + 2]; u.w = s[r][c * 4 + 3];
    *reinterpret_cast<float4*>(&o[(size_t)(nx + r) * EMBED + kx + c * 4]) = u;
}

// ---------------------------------------------------------------------------
// Pipelined GEMM: C[4096,1024] = A @ W^T + bias, tile 128x128x32, 8 warps 2x4.
// A [m][k] and B [n][k] both k-pair-permuted tf32 in gmem; fragments via
// LDS.64 (uint2). 2-stage cp.async pipeline, ONE barrier per k-tile.
// mode 0: write [B,H,S,Dh] (d permuted); mode 2: [B,H,Dh,S] (s permuted);
// mode 3: row-major [M,N] (no perm).
// ---------------------------------------------------------------------------
#define BM 128
#define BN 128
#define BK 32
#define ASTR 40                  /* words; conflict-free for uint2 pattern */
#define BSTR 40
#define A_BUF (BM*ASTR*4)        /* 20480 B */
#define B_BUF (BN*BSTR*4)        /* 20480 B */
#define NSTAGE 2
#define PIPE_SMEM (NSTAGE*(A_BUF+B_BUF))   /* 81920 B */
#define NKT (EMBED/BK)           /* 32 */

__device__ __forceinline__ void
gemm_pipe_body(const float* __restrict__ A, const float* __restrict__ W,
               const float* __restrict__ bias, float* __restrict__ out, int mode)
{
    extern __shared__ char sm[];
    const uint32_t sb = smem_u32(sm);
    const int t    = threadIdx.x;
    const int w    = t >> 5;
    const int lane = t & 31;
    const int gid  = lane >> 2;
    const int tig  = lane & 3;
    const int wm   = w >> 2;
    const int wn   = w & 3;
    const int m0   = blockIdx.y * BM;
    const int n0   = blockIdx.x * BN;

    uint32_t aoff[NSTAGE], boff[NSTAGE];
#pragma unroll
    for (int s = 0; s < NSTAGE; s++) {
        aoff[s] = sb + s * A_BUF;
        boff[s] = sb + NSTAGE * A_BUF + s * B_BUF;
    }

    auto issue = [&](int slot, int k0) {
#pragma unroll
        for (int it = 0; it < 4; it++) {             // A: 1024 16B chunks
            int idx = t + it * 256;
            int r = idx >> 3, c = idx & 7;
            CP16(aoff[slot] + r * (ASTR * 4) + c * 16,
                 A + (size_t)(m0 + r) * EMBED + k0 + c * 4);
        }
#pragma unroll
        for (int it = 0; it < 4; it++) {             // B: 1024 16B chunks
            int idx = t + it * 256;
            int r = idx >> 3, c = idx & 7;
            CP16(boff[slot] + r * (BSTR * 4) + c * 16,
                 W + (size_t)(n0 + r) * EMBED + k0 + c * 4);
        }
        CP_COMMIT();
    };

    float acc[4][4][4];
#pragma unroll
    for (int i = 0; i < 4; i++)
#pragma unroll
        for (int j = 0; j < 4; j++)
#pragma unroll
            for (int r = 0; r < 4; r++) acc[i][j][r] = 0.f;

    issue(0, 0);

    for (int kt = 0; kt < NKT; kt++) {
        const int slot = kt & 1;
        CP_WAIT0();
        __syncthreads();                 // slot data ready; prior compute done
        if (kt + 1 < NKT) issue(slot ^ 1, (kt + 1) * BK);

        const unsigned (*As)[ASTR] = (const unsigned (*)[ASTR])(sm + slot * A_BUF);
        const unsigned (*Bs)[BSTR] =
            (const unsigned (*)[BSTR])(sm + NSTAGE * A_BUF + slot * B_BUF);

#pragma unroll
        for (int kk = 0; kk < BK; kk += 8) {
            unsigned af[4][4], bf[4][2];
#pragma unroll
            for (int i = 0; i < 4; i++) {
                int mb = wm * 64 + i * 16;
                uint2 lo = *reinterpret_cast<const uint2*>(&As[mb + gid    ][kk + 2 * tig]);
                uint2 hi = *reinterpret_cast<const uint2*>(&As[mb + gid + 8][kk + 2 * tig]);
                af[i][0] = lo.x; af[i][1] = hi.x; af[i][2] = lo.y; af[i][3] = hi.y;
            }
#pragma unroll
            for (int j = 0; j < 4; j++) {
                int nb = wn * 32 + j * 8;
                uint2 bb = *reinterpret_cast<const uint2*>(&Bs[nb + gid][kk + 2 * tig]);
                bf[j][0] = bb.x; bf[j][1] = bb.y;
            }
#pragma unroll
            for (int i = 0; i < 4; i++)
#pragma unroll
                for (int j = 0; j < 4; j++)
                    mma8(acc[i][j], af[i], bf[j]);
        }
        // no trailing barrier: next iteration's top barrier orders slot reuse
    }

    // Epilogue (scalar stores; producer-side perms applied here at zero cost)
#pragma unroll
    for (int i = 0; i < 4; i++) {
#pragma unroll
        for (int j = 0; j < 4; j++) {
#pragma unroll
            for (int r = 0; r < 4; r++) {
                int m = m0 + wm * 64 + i * 16 + gid + ((r >> 1) << 3);
                int n = n0 + wn * 32 + j * 8 + 2 * tig + (r & 1);
                float v = acc[i][j][r] + bias[n];
                if (mode == 3) {
                    out[(size_t)m * EMBED + n] = v;
                } else {
                    int b = m >> 11, s = m & (SEQ - 1);
                    int h = n >> 6,  d = n & (HD - 1);
                    if (mode == 2) {
                        int sp = (s & ~7) | pp8(s & 7);      // permute kv (s)
                        out[(((size_t)(b * HEADS + h)) * HD + d) * SEQ + sp] = v;
                    } else {
                        int dp = (d & 56) | pp8(d & 7);      // permute d
                        out[(((size_t)(b * HEADS + h)) * SEQ + s) * HD + dp] = v;
                    }
                }
            }
        }
    }
}

__global__ void __launch_bounds__(256, 2)
gemm_qkv(const float* __restrict__ Xt, const float* __restrict__ Wt,
         const float* __restrict__ bq, const float* __restrict__ bk,
         const float* __restrict__ bv,
         float* __restrict__ Qo, float* __restrict__ Ko, float* __restrict__ Vo)
{
    if (blockIdx.z == 0)
        gemm_pipe_body(Xt, Wt,                 bq, Qo, 0);
    else if (blockIdx.z == 1)
        gemm_pipe_body(Xt, Wt + EMBED*EMBED,   bk, Ko, 0);
    else
        gemm_pipe_body(Xt, Wt + 2*EMBED*EMBED, bv, Vo, 2);
}

__global__ void __launch_bounds__(256, 2)
gemm_out(const float* __restrict__ Aa, const float* __restrict__ Wt,
         const float* __restrict__ bias, float* __restrict__ out)
{
    gemm_pipe_body(Aa, Wt + 3*EMBED*EMBED, bias, out, 3);
}

// ---------------------------------------------------------------------------
// Flash attention. K (d-cols) and Vt (s-cols) arrive pair-permuted, so the
// b-fragment pairs (slot tig, tig+4) are physically adjacent -> uint2 LDS.64.
// A-side (P shuffle, softmax) entirely unchanged; Q a-frags read the same
// permuted physical cols as K so slot<->logical pairing stays consistent.
// FL_STRIDE=72 makes the uint2 pattern bank-conflict-free.
// Epilogue writes g_A with the gemm-k pair-perm (scalar stores, zero cost).
// ---------------------------------------------------------------------------
#define BQ  64
#define BKV 64
#define FL_STRIDE 72
#define TILE_WORDS (BKV * FL_STRIDE)              /* 4608 */
#define FLASH_SMEM_BYTES (4 * TILE_WORDS * 4)     /* 73728 */

__global__ void __launch_bounds__(128, 3)
flash_attn(const float* __restrict__ Q, const float* __restrict__ K,
           const float* __restrict__ Vt, float* __restrict__ outA)
{
    extern __shared__ unsigned sh[];
    unsigned (*Ks0)[FL_STRIDE] = (unsigned (*)[FL_STRIDE])(sh);
    unsigned (*Vs0)[FL_STRIDE] = (unsigned (*)[FL_STRIDE])(sh + TILE_WORDS);
    unsigned (*Ks1)[FL_STRIDE] = (unsigned (*)[FL_STRIDE])(sh + 2 * TILE_WORDS);
    unsigned (*Vs1)[FL_STRIDE] = (unsigned (*)[FL_STRIDE])(sh + 3 * TILE_WORDS);

    const int tid  = threadIdx.x;
    const int w    = tid >> 5;
    const int lane = tid & 31;
    const int gid  = lane >> 2;
    const int tig  = lane & 3;
    const int bh   = blockIdx.y;
    const int q0   = blockIdx.x * BQ;
    const int mq   = w * 16;

    const float* Qp = Q  + (size_t)bh * SEQ * HD;
    const float* Kp = K  + (size_t)bh * SEQ * HD;
    const float* Vp = Vt + (size_t)bh * HD * SEQ;

    const int ldr = tid >> 4;
    const int ldc = (tid & 15) * 4;

    // Stage Q (scaled, tf32) across Ks0||Vs0 (128 rows), pull frags to regs.
    const float QSC = 0.125f * 1.44269504088896340736f;
    unsigned (*Qst)[FL_STRIDE] = Ks0;             // 128 rows contiguous
#pragma unroll
    for (int it = 0; it < 8; it++) {
        int r = ldr + it * 8;
        float4 v = *reinterpret_cast<const float4*>(&Qp[(size_t)(q0 + r) * HD + ldc]);
        v.x *= QSC; v.y *= QSC; v.z *= QSC; v.w *= QSC;
        *reinterpret_cast<uint4*>(&Qst[r][ldc]) = tf4(v);
    }
    __syncthreads();
    unsigned qa[8][4];
#pragma unroll
    for (int kk = 0; kk < 8; kk++) {
        // physical 2*tig / 2*tig+1 hold logical d = tig / tig+4 (slots 0..3 / 4..7)
        uint2 lo = *reinterpret_cast<const uint2*>(&Qst[mq + gid    ][kk * 8 + 2 * tig]);
        uint2 hi = *reinterpret_cast<const uint2*>(&Qst[mq + gid + 8][kk * 8 + 2 * tig]);
        qa[kk][0] = lo.x; qa[kk][1] = hi.x; qa[kk][2] = lo.y; qa[kk][3] = hi.y;
    }
    __syncthreads();

    // Prologue: tile 0
#pragma unroll
    for (int it = 0; it < 8; it++) {
        int r = ldr + it * 8;
        float4 kv = *reinterpret_cast<const float4*>(&Kp[(size_t)r * HD + ldc]);
        *reinterpret_cast<uint4*>(&Ks0[r][ldc]) = tf4(kv);
        float4 vv = *reinterpret_cast<const float4*>(&Vp[(size_t)r * SEQ + ldc]);
        *reinterpret_cast<uint4*>(&Vs0[r][ldc]) = tf4(vv);
    }
    __syncthreads();

    float o[8][4];
#pragma unroll
    for (int j = 0; j < 8; j++)
#pragma unroll
        for (int r = 0; r < 4; r++) o[j][r] = 0.f;
    float mrow[2] = {-1e30f, -1e30f};
    float lrow[2] = {0.f, 0.f};

    const int l0 = (lane & 28) | (tig >> 1);
    const bool odd = (tig & 1);

    for (int kb = 0; kb < SEQ / BKV; kb++) {
        unsigned (*Kc)[FL_STRIDE] = (kb & 1) ? Ks1 : Ks0;
        unsigned (*Vc)[FL_STRIDE] = (kb & 1) ? Vs1 : Vs0;
        unsigned (*Kn)[FL_STRIDE] = (kb & 1) ? Ks0 : Ks1;
        unsigned (*Vn)[FL_STRIDE] = (kb & 1) ? Vs0 : Vs1;
        const bool has_next = (kb + 1) < (SEQ / BKV);
        const int sN = (kb + 1) * BKV;

        float4 ld[8];
        if (has_next) {
#pragma unroll
            for (int it = 0; it < 8; it++) {
                int r = ldr + it * 8;
                ld[it] = *reinterpret_cast<const float4*>(&Kp[(size_t)(sN + r) * HD + ldc]);
            }
        }

        // S = Q @ K^T  (b-frags: one LDS.64 per (j,kk))
        float s[8][4];
#pragma unroll
        for (int j = 0; j < 8; j++)
#pragma unroll
            for (int r = 0; r < 4; r++) s[j][r] = 0.f;
#pragma unroll
        for (int kk = 0; kk < 8; kk++) {
#pragma unroll
            for (int j = 0; j < 8; j++) {
                uint2 bb = *reinterpret_cast<const uint2*>(&Kc[j * 8 + gid][kk * 8 + 2 * tig]);
                unsigned b[2] = { bb.x, bb.y };
                mma8(s[j], qa[kk], b);
            }
        }

        if (has_next) {
#pragma unroll
            for (int it = 0; it < 8; it++) {
                int r = ldr + it * 8;
                *reinterpret_cast<uint4*>(&Kn[r][ldc]) = tf4(ld[it]);
                ld[it] = *reinterpret_cast<const float4*>(&Vp[(size_t)r * SEQ + sN + ldc]);
            }
        }

        // Online softmax (base 2)
#pragma unroll
        for (int rr = 0; rr < 2; rr++) {
            float mx = -1e30f;
#pragma unroll
            for (int j = 0; j < 8; j++) {
                mx = fmaxf(mx, s[j][rr * 2]);
                mx = fmaxf(mx, s[j][rr * 2 + 1]);
            }
            mx = fmaxf(mx, __shfl_xor_sync(0xffffffffu, mx, 1));
            mx = fmaxf(mx, __shfl_xor_sync(0xffffffffu, mx, 2));
            float mnew = fmaxf(mrow[rr], mx);
            float corr = ex2(mrow[rr] - mnew);
            float rs = 0.f;
#pragma unroll
            for (int j = 0; j < 8; j++) {
                float e0 = ex2(s[j][rr * 2]     - mnew);
                float e1 = ex2(s[j][rr * 2 + 1] - mnew);
                s[j][rr * 2] = e0; s[j][rr * 2 + 1] = e1;
                rs += e0 + e1;
            }
            rs += __shfl_xor_sync(0xffffffffu, rs, 1);
            rs += __shfl_xor_sync(0xffffffffu, rs, 2);
            lrow[rr] = lrow[rr] * corr + rs;
            mrow[rr] = mnew;
#pragma unroll
            for (int j = 0; j < 8; j++) {
                o[j][rr * 2]     *= corr;
                o[j][rr * 2 + 1] *= corr;
            }
        }

        // O += P @ V  (P A-side logical, unchanged; V b-frags LDS.64)
#pragma unroll
        for (int j = 0; j < 8; j++) {
            unsigned v0 = f2tf(s[j][0]), v1 = f2tf(s[j][1]);
            unsigned v2 = f2tf(s[j][2]), v3 = f2tf(s[j][3]);
            unsigned t00 = __shfl_sync(0xffffffffu, v0, l0);
            unsigned t01 = __shfl_sync(0xffffffffu, v1, l0);
            unsigned t02 = __shfl_sync(0xffffffffu, v2, l0);
            unsigned t03 = __shfl_sync(0xffffffffu, v3, l0);
            unsigned t10 = __shfl_sync(0xffffffffu, v0, l0 + 2);
            unsigned t11 = __shfl_sync(0xffffffffu, v1, l0 + 2);
            unsigned t12 = __shfl_sync(0xffffffffu, v2, l0 + 2);
            unsigned t13 = __shfl_sync(0xffffffffu, v3, l0 + 2);
            unsigned a[4];
            a[0] = odd ? t01 : t00;
            a[1] = odd ? t03 : t02;
            a[2] = odd ? t11 : t10;
            a[3] = odd ? t13 : t12;
#pragma unroll
            for (int jj = 0; jj < 8; jj++) {
                uint2 bb = *reinterpret_cast<const uint2*>(&Vc[jj * 8 + gid][j * 8 + 2 * tig]);
                unsigned b[2] = { bb.x, bb.y };
                mma8(o[jj], a, b);
            }
        }

        if (has_next) {
#pragma unroll
            for (int it = 0; it < 8; it++) {
                int r = ldr + it * 8;
                *reinterpret_cast<uint4*>(&Vn[r][ldc]) = tf4(ld[it]);
            }
        }
        __syncthreads();
    }

    // Epilogue: cols written with the gemm k pair-perm (gemm_out's A input).
    const int b = bh >> 4, h = bh & 15;
    const float inv0 = 1.f / lrow[0];
    const float inv1 = 1.f / lrow[1];
    const int row0 = q0 + mq + gid;
    const int row1 = row0 + 8;
    const int cofs = (tig < 2) ? 4 * tig : 4 * tig - 7;  // phys of logical 2*tig
#pragma unroll
    for (int jj = 0; jj < 8; jj++) {
        int c0 = h * HD + jj * 8 + cofs;                 // pair partner at +2
        outA[(size_t)(b * SEQ + row0) * EMBED + c0    ] =
            __uint_as_float(f2tf(o[jj][0] * inv0));
        outA[(size_t)(b * SEQ + row0) * EMBED + c0 + 2] =
            __uint_as_float(f2tf(o[jj][1] * inv0));
        outA[(size_t)(b * SEQ + row1) * EMBED + c0    ] =
            __uint_as_float(f2tf(o[jj][2] * inv1));
        outA[(size_t)(b * SEQ + row1) * EMBED + c0 + 2] =
            __uint_as_float(f2tf(o[jj][3] * inv1));
    }
}

// ---------------------------------------------------------------------------
// Launch
// ---------------------------------------------------------------------------
extern "C" void kernel_launch(void* const* d_in, const int* in_sizes, int n_in,
                              void* d_out, int out_size)
{
    const float* X  = (const float*)d_in[0];
    const float* Wq = (const float*)d_in[1];
    const float* bq = (const float*)d_in[2];
    const float* Wk = (const float*)d_in[3];
    const float* bk = (const float*)d_in[4];
    const float* Wv = (const float*)d_in[5];
    const float* bv = (const float*)d_in[6];
    const float* Wo = (const float*)d_in[7];
    const float* bo = (const float*)d_in[8];
    float* out = (float*)d_out;

    float *qb, *kb, *vtb, *ab, *xtb, *wtb;
    cudaGetSymbolAddress((void**)&qb,  g_Q);
    cudaGetSymbolAddress((void**)&kb,  g_K);
    cudaGetSymbolAddress((void**)&vtb, g_Vt);
    cudaGetSymbolAddress((void**)&ab,  g_A);
    cudaGetSymbolAddress((void**)&xtb, g_Xt);
    cudaGetSymbolAddress((void**)&wtb, g_Wt);

    cudaFuncSetAttribute(flash_attn, cudaFuncAttributeMaxDynamicSharedMemorySize,
                         FLASH_SMEM_BYTES);
    cudaFuncSetAttribute(gemm_qkv, cudaFuncAttributeMaxDynamicSharedMemorySize,
                         PIPE_SMEM);
    cudaFuncSetAttribute(gemm_out, cudaFuncAttributeMaxDynamicSharedMemorySize,
                         PIPE_SMEM);

    // 1) prep: X tf32 + k-perm; W transpose + tf32 + k-perm
    prep_x<<<(MROWS * EMBED / 4) / 256, 256>>>(X, xtb);
    dim3 wgrid(EMBED / 32, EMBED / 32, 4);
    prep_w<<<wgrid, 256>>>(Wq, Wk, Wv, Wo, wtb);

    // 2) fused QKV projections
    dim3 qkvgrid(EMBED / BN, MROWS / BM, 3);     // (8, 32, 3)
    gemm_qkv<<<qkvgrid, 256, PIPE_SMEM>>>(xtb, wtb, bq, bk, bv, qb, kb, vtb);

    // 3) attention
    dim3 fgrid(SEQ / BQ, BATCH * HEADS);         // (32, 32)
    flash_attn<<<fgrid, 128, FLASH_SMEM_BYTES>>>(qb, kb, vtb, ab);

    // 4) output projection
    dim3 ogrid(EMBED / BN, MROWS / BM);          // (8, 32)
    gemm_out<<<ogrid, 256, PIPE_SMEM>>>(ab, wtb, bo, out);
}